// round 2
// baseline (speedup 1.0000x reference)
#include <cuda_runtime.h>
#include <math.h>

#define TT 2048
#define CC 1024
#define HH 16
#define DD 64
#define EE 8
#define FF 4096

// ------------------------- scratch (device globals; no allocs) ---------------
__device__ float g_xn  [TT * CC];          // LN1 output
__device__ float g_q   [HH * TT * DD];     // (H,T,D)
__device__ float g_k   [HH * TT * DD];
__device__ float g_v   [HH * TT * DD];
__device__ float g_att [TT * CC];          // concat-head attention output
__device__ float g_xn2 [TT * CC];          // LN2 output
__device__ float g_Hbuf[(size_t)TT * 2 * FF];  // expert hidden, slot-indexed (64MB)
__device__ float g_O2  [(size_t)TT * 2 * CC];  // expert output * gate, slot-indexed
__device__ float g_gate[TT * 2];
__device__ int   g_list[EE * TT];
__device__ int   g_count[EE];

// ------------------------------ LayerNorm ------------------------------------
template <int PHASE>
__global__ void ln_kernel(const float* __restrict__ x,
                          const float* __restrict__ gamma,
                          const float* __restrict__ beta)
{
    int t = blockIdx.x;
    const float* xr = x + (size_t)t * CC;
    float s = 0.f, s2 = 0.f;
    for (int c = threadIdx.x; c < CC; c += 256) {
        float v = xr[c]; s += v; s2 += v * v;
    }
#pragma unroll
    for (int o = 16; o > 0; o >>= 1) {
        s  += __shfl_xor_sync(0xffffffffu, s,  o);
        s2 += __shfl_xor_sync(0xffffffffu, s2, o);
    }
    __shared__ float sm[8], sm2[8];
    __shared__ float smean, srstd;
    if ((threadIdx.x & 31) == 0) { sm[threadIdx.x >> 5] = s; sm2[threadIdx.x >> 5] = s2; }
    __syncthreads();
    if (threadIdx.x == 0) {
        float a = 0.f, a2 = 0.f;
        for (int i = 0; i < 8; i++) { a += sm[i]; a2 += sm2[i]; }
        float m   = a * (1.f / CC);
        float var = a2 * (1.f / CC) - m * m;
        smean = m; srstd = rsqrtf(var + 1e-5f);
    }
    __syncthreads();
    float m = smean, r = srstd;
    float* out = (PHASE == 0) ? g_xn : g_xn2;
    for (int c = threadIdx.x; c < CC; c += 256)
        out[(size_t)t * CC + c] = (xr[c] - m) * r * gamma[c] + beta[c];
}

// ------------------------------ GEMM -----------------------------------------
// MODE 0: QKV   A=g_xn (T,C)  B=W{q,k,v} head-blocked (H,C,D)   out (H,T,D), sel picks q/k/v
// MODE 1: proj  A=g_att       B=Wproj (C,C) row-major           out = acc + bproj + x -> d_out
// MODE 2: FFN1  A=g_xn2 gathered by list  B=W1[e] (C,F)         out = relu(acc + b1) -> g_Hbuf[slot]
// MODE 3: FFN2  A=g_Hbuf gathered         B=W2[e] (F,C)         out = gate*(acc + b2) -> g_O2[slot]
#define BM 128
#define BN 128
#define BK 16

template <int MODE>
__global__ __launch_bounds__(256)
void gemm_kernel(const float* __restrict__ B,
                 const float* __restrict__ bias,
                 const float* __restrict__ resid,
                 float* __restrict__ Cout,
                 int Kdim, int Ndim, int sel)
{
    const int tid = threadIdx.x;
    const int mtile = blockIdx.y, ntile = blockIdx.x;
    const int e = blockIdx.z;

    int Mcount = TT;
    const int* list = nullptr;
    const float* Bp = B;
    const float* biasp = bias;
    if (MODE >= 2) {
        Mcount = g_count[e];
        if (mtile * BM >= Mcount) return;
        list  = g_list + e * TT;
        Bp    = B + (size_t)e * Kdim * Ndim;
        biasp = bias + (size_t)e * Ndim;
    }

    __shared__ float As[BK][BM + 4];
    __shared__ float Bs[BK][BN + 4];

    const int tx = tid & 15, ty = tid >> 4;
    float acc[8][8];
#pragma unroll
    for (int i = 0; i < 8; i++)
#pragma unroll
        for (int j = 0; j < 8; j++) acc[i][j] = 0.f;

    const int arow = tid >> 2;         // 0..63
    const int kcol = (tid & 3) * 4;    // 0,4,8,12
    const float* aptr[2];
#pragma unroll
    for (int i = 0; i < 2; i++) {
        int r = mtile * BM + arow + i * 64;
        if (MODE == 0)      aptr[i] = g_xn  + (size_t)r * CC;
        else if (MODE == 1) aptr[i] = g_att + (size_t)r * CC;
        else if (r < Mcount) {
            int slot = list[r];
            aptr[i] = (MODE == 2) ? (g_xn2  + (size_t)(slot >> 1) * CC)
                                  : (g_Hbuf + (size_t)slot * FF);
        } else aptr[i] = nullptr;
    }

    const int bk = tid >> 5;           // 0..7
    const int bn = (tid & 31) * 4;     // 0..124

    for (int k0 = 0; k0 < Kdim; k0 += BK) {
#pragma unroll
        for (int i = 0; i < 2; i++) {
            float4 va = aptr[i] ? *(const float4*)(aptr[i] + k0 + kcol)
                                : make_float4(0.f, 0.f, 0.f, 0.f);
            int r = arow + i * 64;
            As[kcol + 0][r] = va.x; As[kcol + 1][r] = va.y;
            As[kcol + 2][r] = va.z; As[kcol + 3][r] = va.w;
        }
#pragma unroll
        for (int i = 0; i < 2; i++) {
            int kr = bk + i * 8;
            const float* bptr;
            if (MODE == 0) {
                int n = ntile * BN + bn;
                int h = n >> 6, nd = n & 63;
                bptr = Bp + ((size_t)h * Kdim + (k0 + kr)) * 64 + nd;
            } else {
                bptr = Bp + (size_t)(k0 + kr) * Ndim + ntile * BN + bn;
            }
            float4 vb = *(const float4*)bptr;
            *(float4*)&Bs[kr][bn] = vb;
        }
        __syncthreads();
#pragma unroll
        for (int kk = 0; kk < BK; kk++) {
            float ra[8], rb[8];
            *(float4*)&ra[0] = *(const float4*)&As[kk][ty * 8];
            *(float4*)&ra[4] = *(const float4*)&As[kk][ty * 8 + 4];
            *(float4*)&rb[0] = *(const float4*)&Bs[kk][tx * 8];
            *(float4*)&rb[4] = *(const float4*)&Bs[kk][tx * 8 + 4];
#pragma unroll
            for (int i = 0; i < 8; i++)
#pragma unroll
                for (int j = 0; j < 8; j++)
                    acc[i][j] = fmaf(ra[i], rb[j], acc[i][j]);
        }
        __syncthreads();
    }

    const int n0 = ntile * BN + tx * 8;
    if (MODE == 0) {
        float* outbase = (sel == 0) ? g_q : (sel == 1) ? g_k : g_v;
        int h = n0 >> 6, d0 = n0 & 63;
#pragma unroll
        for (int i = 0; i < 8; i++) {
            int m = mtile * BM + ty * 8 + i;
            float* op = outbase + ((size_t)h * TT + m) * DD + d0;
            *(float4*)op       = make_float4(acc[i][0], acc[i][1], acc[i][2], acc[i][3]);
            *(float4*)(op + 4) = make_float4(acc[i][4], acc[i][5], acc[i][6], acc[i][7]);
        }
    } else if (MODE == 1) {
#pragma unroll
        for (int i = 0; i < 8; i++) {
            int m = mtile * BM + ty * 8 + i;
            size_t base = (size_t)m * CC + n0;
#pragma unroll
            for (int j = 0; j < 8; j++)
                Cout[base + j] = acc[i][j] + bias[n0 + j] + resid[base + j];
        }
    } else {
#pragma unroll
        for (int i = 0; i < 8; i++) {
            int r = mtile * BM + ty * 8 + i;
            if (r >= Mcount) continue;
            int slot = list[r];
            if (MODE == 2) {
                float* op = g_Hbuf + (size_t)slot * FF + n0;
#pragma unroll
                for (int j = 0; j < 8; j++)
                    op[j] = fmaxf(acc[i][j] + biasp[n0 + j], 0.f);
            } else {
                float gte = g_gate[slot];
                float* op = g_O2 + (size_t)slot * CC + n0;
#pragma unroll
                for (int j = 0; j < 8; j++)
                    op[j] = gte * (acc[i][j] + biasp[n0 + j]);
            }
        }
    }
}

// ------------------------- Flash attention (causal) --------------------------
// Per block: one (head, 64-row query tile). NOTE: reference scales by C^-0.5.
__global__ __launch_bounds__(256)
void attn_kernel()
{
    const int qt  = blockIdx.x;   // 0..31
    const int h   = blockIdx.y;   // 0..15
    const int tid = threadIdx.x;
    const int tx  = tid & 15, ty = tid >> 4;

    __shared__ float QT[64 * 64];  // QT[d*64 + row]
    __shared__ float KP[64 * 64];  // phase1: K^T[d*64+key]; phase2: P[row*64+s]
    __shared__ float Vs[64 * 64];  // Vs[s*64 + d]

    const float scale = 0.03125f;  // C^-0.5 = 1/32

    const float* Qg = g_q + ((size_t)h * TT + qt * 64) * DD;
#pragma unroll
    for (int i = 0; i < 4; i++) {
        int o = i * 1024 + tid * 4;
        float4 v = *(const float4*)(Qg + o);
        int r = o >> 6, d = o & 63;
        QT[(d + 0) * 64 + r] = v.x; QT[(d + 1) * 64 + r] = v.y;
        QT[(d + 2) * 64 + r] = v.z; QT[(d + 3) * 64 + r] = v.w;
    }

    float O[4][4], mrow[4], lrow[4];
#pragma unroll
    for (int i = 0; i < 4; i++) {
        mrow[i] = -1e30f; lrow[i] = 0.f;
#pragma unroll
        for (int j = 0; j < 4; j++) O[i][j] = 0.f;
    }

    for (int kt = 0; kt <= qt; kt++) {
        __syncthreads();  // previous iter done with KP/Vs (also orders QT on iter 0)
        const float* Kg = g_k + ((size_t)h * TT + kt * 64) * DD;
        const float* Vg = g_v + ((size_t)h * TT + kt * 64) * DD;
#pragma unroll
        for (int i = 0; i < 4; i++) {
            int o = i * 1024 + tid * 4;
            float4 kv = *(const float4*)(Kg + o);
            int r = o >> 6, d = o & 63;
            KP[(d + 0) * 64 + r] = kv.x; KP[(d + 1) * 64 + r] = kv.y;
            KP[(d + 2) * 64 + r] = kv.z; KP[(d + 3) * 64 + r] = kv.w;
            *(float4*)&Vs[o] = *(const float4*)(Vg + o);
        }
        __syncthreads();

        float s[4][4];
#pragma unroll
        for (int i = 0; i < 4; i++)
#pragma unroll
            for (int j = 0; j < 4; j++) s[i][j] = 0.f;
#pragma unroll 4
        for (int d = 0; d < 64; d++) {
            float4 qv = *(const float4*)&QT[d * 64 + ty * 4];
            float4 kv = *(const float4*)&KP[d * 64 + tx * 4];
            float qa[4] = {qv.x, qv.y, qv.z, qv.w};
            float ka[4] = {kv.x, kv.y, kv.z, kv.w};
#pragma unroll
            for (int i = 0; i < 4; i++)
#pragma unroll
                for (int j = 0; j < 4; j++)
                    s[i][j] = fmaf(qa[i], ka[j], s[i][j]);
        }
#pragma unroll
        for (int i = 0; i < 4; i++)
#pragma unroll
            for (int j = 0; j < 4; j++) {
                float v = s[i][j] * scale;
                if (kt == qt && (tx * 4 + j) > (ty * 4 + i)) v = -1e30f;
                s[i][j] = v;
            }

        float p[4][4], fac[4];
#pragma unroll
        for (int i = 0; i < 4; i++) {
            float m = fmaxf(fmaxf(s[i][0], s[i][1]), fmaxf(s[i][2], s[i][3]));
#pragma unroll
            for (int o = 8; o > 0; o >>= 1)
                m = fmaxf(m, __shfl_xor_sync(0xffffffffu, m, o));
            float mn = fmaxf(mrow[i], m);
            fac[i] = __expf(mrow[i] - mn);
            float sum = 0.f;
#pragma unroll
            for (int j = 0; j < 4; j++) { p[i][j] = __expf(s[i][j] - mn); sum += p[i][j]; }
#pragma unroll
            for (int o = 8; o > 0; o >>= 1)
                sum += __shfl_xor_sync(0xffffffffu, sum, o);
            mrow[i] = mn;
            lrow[i] = lrow[i] * fac[i] + sum;
        }
        __syncthreads();  // everyone done reading KP-as-K (and mrow is per-thread)
#pragma unroll
        for (int i = 0; i < 4; i++)
            *(float4*)&KP[(ty * 4 + i) * 64 + tx * 4] =
                make_float4(p[i][0], p[i][1], p[i][2], p[i][3]);
        __syncthreads();
#pragma unroll
        for (int i = 0; i < 4; i++)
#pragma unroll
            for (int j = 0; j < 4; j++) O[i][j] *= fac[i];
        for (int sidx = 0; sidx < 64; sidx++) {
            float4 vv = *(const float4*)&Vs[sidx * 64 + tx * 4];
            float va[4] = {vv.x, vv.y, vv.z, vv.w};
#pragma unroll
            for (int i = 0; i < 4; i++) {
                float pv = KP[(ty * 4 + i) * 64 + sidx];
#pragma unroll
                for (int j = 0; j < 4; j++)
                    O[i][j] = fmaf(pv, va[j], O[i][j]);
            }
        }
    }

#pragma unroll
    for (int i = 0; i < 4; i++) {
        float inv = 1.f / lrow[i];
        int t = qt * 64 + ty * 4 + i;
        float* op = g_att + (size_t)t * CC + h * DD + tx * 4;
        *(float4*)op = make_float4(O[i][0] * inv, O[i][1] * inv,
                                   O[i][2] * inv, O[i][3] * inv);
    }
}

// ------------------------------ Router ---------------------------------------
__global__ void zero_counts_kernel() { if (threadIdx.x < EE) g_count[threadIdx.x] = 0; }

__global__ void router_kernel(const float* __restrict__ Wr, const float* __restrict__ br,
                              const float* __restrict__ Wn, const float* __restrict__ bn,
                              const float* __restrict__ noise)
{
    int t = blockIdx.x * 8 + (threadIdx.x >> 5);
    int lane = threadIdx.x & 31;
    const float* xr = g_xn2 + (size_t)t * CC;
    float ar[8] = {0,0,0,0,0,0,0,0}, an[8] = {0,0,0,0,0,0,0,0};
    for (int c = lane; c < CC; c += 32) {
        float xv = xr[c];
        float4 w0 = *(const float4*)(Wr + c * 8);
        float4 w1 = *(const float4*)(Wr + c * 8 + 4);
        ar[0] += xv * w0.x; ar[1] += xv * w0.y; ar[2] += xv * w0.z; ar[3] += xv * w0.w;
        ar[4] += xv * w1.x; ar[5] += xv * w1.y; ar[6] += xv * w1.z; ar[7] += xv * w1.w;
        float4 n0 = *(const float4*)(Wn + c * 8);
        float4 n1 = *(const float4*)(Wn + c * 8 + 4);
        an[0] += xv * n0.x; an[1] += xv * n0.y; an[2] += xv * n0.z; an[3] += xv * n0.w;
        an[4] += xv * n1.x; an[5] += xv * n1.y; an[6] += xv * n1.z; an[7] += xv * n1.w;
    }
#pragma unroll
    for (int e = 0; e < 8; e++) {
#pragma unroll
        for (int o = 16; o > 0; o >>= 1) {
            ar[e] += __shfl_xor_sync(0xffffffffu, ar[e], o);
            an[e] += __shfl_xor_sync(0xffffffffu, an[e], o);
        }
    }
    if (lane == 0) {
        float noisy[8];
#pragma unroll
        for (int e = 0; e < 8; e++) {
            float l  = ar[e] + br[e];
            float nl = an[e] + bn[e];
            float sp = (nl > 20.f) ? nl : log1pf(expf(nl));
            noisy[e] = l + noise[t * 8 + e] * sp;
        }
        int i1 = 0;
        for (int e = 1; e < 8; e++) if (noisy[e] > noisy[i1]) i1 = e;
        int i2 = (i1 == 0) ? 1 : 0;
        for (int e = 0; e < 8; e++)
            if (e != i1 && noisy[e] > noisy[i2]) i2 = e;
        float ee = expf(noisy[i2] - noisy[i1]);
        float z  = 1.f + ee;
        float g1 = 1.f / z, g2 = ee / z;
        int p1 = atomicAdd(&g_count[i1], 1);
        g_list[i1 * TT + p1] = t * 2;     g_gate[t * 2]     = g1;
        int p2 = atomicAdd(&g_count[i2], 1);
        g_list[i2 * TT + p2] = t * 2 + 1; g_gate[t * 2 + 1] = g2;
    }
}

// ------------------------------ Combine --------------------------------------
__global__ void combine_kernel(float* __restrict__ out)
{
    int t = blockIdx.x;
    size_t b0 = (size_t)(t * 2) * CC;
    size_t b1 = (size_t)(t * 2 + 1) * CC;
    for (int c = threadIdx.x; c < CC; c += 256)
        out[(size_t)t * CC + c] += g_O2[b0 + c] + g_O2[b1 + c];
}

// ------------------------------ launch ---------------------------------------
extern "C" void kernel_launch(void* const* d_in, const int* in_sizes, int n_in,
                              void* d_out, int out_size)
{
    (void)in_sizes; (void)n_in; (void)out_size;
    const float* x     = (const float*)d_in[0];
    const float* noise = (const float*)d_in[1];
    const float* ln1_g = (const float*)d_in[2];
    const float* ln1_b = (const float*)d_in[3];
    const float* ln2_g = (const float*)d_in[4];
    const float* ln2_b = (const float*)d_in[5];
    const float* Wq    = (const float*)d_in[6];
    const float* Wk    = (const float*)d_in[7];
    const float* Wv    = (const float*)d_in[8];
    const float* Wproj = (const float*)d_in[9];
    const float* bproj = (const float*)d_in[10];
    const float* Wr    = (const float*)d_in[11];
    const float* br    = (const float*)d_in[12];
    const float* Wn    = (const float*)d_in[13];
    const float* bn    = (const float*)d_in[14];
    const float* W1    = (const float*)d_in[15];
    const float* b1    = (const float*)d_in[16];
    const float* W2    = (const float*)d_in[17];
    const float* b2    = (const float*)d_in[18];
    float* out = (float*)d_out;

    ln_kernel<0><<<TT, 256>>>(x, ln1_g, ln1_b);

    dim3 gqkv(CC / BN, TT / BM);
    gemm_kernel<0><<<gqkv, 256>>>(Wq, nullptr, nullptr, nullptr, CC, CC, 0);
    gemm_kernel<0><<<gqkv, 256>>>(Wk, nullptr, nullptr, nullptr, CC, CC, 1);
    gemm_kernel<0><<<gqkv, 256>>>(Wv, nullptr, nullptr, nullptr, CC, CC, 2);

    attn_kernel<<<dim3(TT / 64, HH), 256>>>();

    gemm_kernel<1><<<dim3(CC / BN, TT / BM), 256>>>(Wproj, bproj, x, out, CC, CC, 0);

    ln_kernel<1><<<TT, 256>>>(out, ln2_g, ln2_b);

    zero_counts_kernel<<<1, 32>>>();
    router_kernel<<<TT / 8, 256>>>(Wr, br, Wn, bn, noise);

    gemm_kernel<2><<<dim3(FF / BN, TT / BM, EE), 256>>>(W1, b1, nullptr, nullptr, CC, FF, 0);
    gemm_kernel<3><<<dim3(CC / BN, TT / BM, EE), 256>>>(W2, b2, nullptr, nullptr, FF, CC, 0);

    combine_kernel<<<TT, 256>>>(out);
}

// round 8
// speedup vs baseline: 2.4934x; 2.4934x over previous
#include <cuda_runtime.h>
#include <math.h>

#define TT 2048
#define CC 1024
#define HH 16
#define DD 64
#define EE 8
#define FF 4096

// ------------------------- scratch (device globals; no allocs) ---------------
__device__ float g_xn  [TT * CC];          // LN1 output
__device__ float g_q   [HH * TT * DD];     // (H,T,D)
__device__ float g_k   [HH * TT * DD];
__device__ float g_v   [HH * TT * DD];
__device__ float g_att [TT * CC];          // concat-head attention output
__device__ float g_xn2 [TT * CC];          // LN2 output
__device__ float g_Hbuf[(size_t)TT * 2 * FF];  // expert hidden, slot-indexed
__device__ float g_O2  [(size_t)TT * 2 * CC];  // expert output * gate, slot-indexed
__device__ float g_gate[TT * 2];
__device__ int   g_list[EE * TT];
__device__ int   g_count[EE];

// ------------------------------ helpers --------------------------------------
__device__ __forceinline__ float to_tf32(float x) {
    float r;
    asm("cvt.rna.tf32.f32 %0, %1;" : "=f"(r) : "f"(x));
    return r;
}

__device__ __forceinline__ void mma_tf32(float* c, const unsigned* a, const unsigned* b) {
    asm volatile(
        "mma.sync.aligned.m16n8k8.row.col.f32.tf32.tf32.f32 "
        "{%0,%1,%2,%3}, {%4,%5,%6,%7}, {%8,%9}, {%0,%1,%2,%3};"
        : "+f"(c[0]), "+f"(c[1]), "+f"(c[2]), "+f"(c[3])
        : "r"(a[0]), "r"(a[1]), "r"(a[2]), "r"(a[3]), "r"(b[0]), "r"(b[1]));
}

// ------------------------------ LayerNorm ------------------------------------
template <int PHASE>
__global__ void ln_kernel(const float* __restrict__ x,
                          const float* __restrict__ gamma,
                          const float* __restrict__ beta)
{
    int t = blockIdx.x;
    const float* xr = x + (size_t)t * CC;
    float s = 0.f, s2 = 0.f;
    for (int c = threadIdx.x; c < CC; c += 256) {
        float v = xr[c]; s += v; s2 += v * v;
    }
#pragma unroll
    for (int o = 16; o > 0; o >>= 1) {
        s  += __shfl_xor_sync(0xffffffffu, s,  o);
        s2 += __shfl_xor_sync(0xffffffffu, s2, o);
    }
    __shared__ float sm[8], sm2[8];
    __shared__ float smean, srstd;
    if ((threadIdx.x & 31) == 0) { sm[threadIdx.x >> 5] = s; sm2[threadIdx.x >> 5] = s2; }
    __syncthreads();
    if (threadIdx.x == 0) {
        float a = 0.f, a2 = 0.f;
        for (int i = 0; i < 8; i++) { a += sm[i]; a2 += sm2[i]; }
        float m   = a * (1.f / CC);
        float var = a2 * (1.f / CC) - m * m;
        smean = m; srstd = rsqrtf(var + 1e-5f);
    }
    __syncthreads();
    float m = smean, r = srstd;
    float* out = (PHASE == 0) ? g_xn : g_xn2;
    for (int c = threadIdx.x; c < CC; c += 256)
        out[(size_t)t * CC + c] = (xr[c] - m) * r * gamma[c] + beta[c];
}

// ------------------------------ tensor-core GEMM -----------------------------
// Tile 128x128, BK=16, 256 threads (8 warps), warp tile 32x64 via m16n8k8 tf32.
// MODE 0: QKV fused  A=g_xn  B in {Wq,Wk,Wv} by blockIdx.z     out (H,T,D)
// MODE 1: proj       A=g_att B=Wproj (C,C)                     out = acc+bias+resid
// MODE 2: FFN1       A=g_xn2 gathered  B=W1[e] (C,F)           relu -> g_Hbuf[slot]
// MODE 3: FFN2       A=g_Hbuf gathered B=W2[e] (F,C)           gate*(..) -> g_O2[slot]
template <int MODE>
__global__ __launch_bounds__(256)
void gemm_kernel(const float* __restrict__ B,
                 const float* __restrict__ B2,
                 const float* __restrict__ B3,
                 const float* __restrict__ bias,
                 const float* __restrict__ resid,
                 float* __restrict__ Cout,
                 int Kdim, int Ndim)
{
    const int tid = threadIdx.x;
    const int mtile = blockIdx.y, ntile = blockIdx.x;
    const int e = blockIdx.z;   // expert (MODE>=2) or qkv-select (MODE 0)

    int Mcount = TT;
    const int* list = nullptr;
    const float* Bp = B;
    const float* biasp = bias;
    if (MODE == 0) {
        Bp = (e == 0) ? B : (e == 1) ? B2 : B3;
    } else if (MODE >= 2) {
        Mcount = g_count[e];
        if (mtile * 128 >= Mcount) return;
        list  = g_list + e * TT;
        Bp    = B + (size_t)e * Kdim * Ndim;
        biasp = bias + (size_t)e * Ndim;
    }

    __shared__ float As[128][20];    // [m][k]
    __shared__ float Bs[16][136];    // [k][n], stride 136 (mod 32 = 8, conflict-free frags)

    const int wid = tid >> 5, lane = tid & 31;
    const int wm = wid & 3, wn = wid >> 2;   // warp grid: 4 (M) x 2 (N)
    const int g = lane >> 2, t = lane & 3;

    // A global loading: 2 threads per row, 8 floats each
    const int arow = tid >> 1;
    const int akh  = (tid & 1) * 8;
    const float* aptr = nullptr;
    {
        int r = mtile * 128 + arow;
        if (MODE == 0)      aptr = g_xn  + (size_t)r * CC;
        else if (MODE == 1) aptr = g_att + (size_t)r * CC;
        else if (r < Mcount) {
            int slot = list[r];
            aptr = (MODE == 2) ? (g_xn2  + (size_t)(slot >> 1) * CC)
                               : (g_Hbuf + (size_t)slot * FF);
        }
    }
    // B global loading: row k = tid>>4, 8 cols
    const int bk = tid >> 4;
    const int bn = (tid & 15) * 8;
    const float* bptr;
    size_t bstride;
    if (MODE == 0) {
        int n = ntile * 128 + bn;
        int hh = n >> 6, d = n & 63;
        bptr = Bp + ((size_t)hh * Kdim + bk) * 64 + d;
        bstride = 64;
    } else {
        bptr = Bp + (size_t)bk * Ndim + ntile * 128 + bn;
        bstride = (size_t)Ndim;
    }

    float4 pa0, pa1, pb0, pb1;
    if (aptr) { pa0 = *(const float4*)(aptr + akh); pa1 = *(const float4*)(aptr + akh + 4); }
    else      { pa0 = make_float4(0,0,0,0); pa1 = pa0; }
    pb0 = *(const float4*)(bptr);
    pb1 = *(const float4*)(bptr + 4);

    float acc[2][8][4];
#pragma unroll
    for (int i = 0; i < 2; i++)
#pragma unroll
        for (int j = 0; j < 8; j++)
#pragma unroll
            for (int q = 0; q < 4; q++) acc[i][j][q] = 0.f;

    for (int k0 = 0; k0 < Kdim; k0 += 16) {
        *(float4*)&As[arow][akh] =
            make_float4(to_tf32(pa0.x), to_tf32(pa0.y), to_tf32(pa0.z), to_tf32(pa0.w));
        *(float4*)&As[arow][akh + 4] =
            make_float4(to_tf32(pa1.x), to_tf32(pa1.y), to_tf32(pa1.z), to_tf32(pa1.w));
        *(float4*)&Bs[bk][bn] =
            make_float4(to_tf32(pb0.x), to_tf32(pb0.y), to_tf32(pb0.z), to_tf32(pb0.w));
        *(float4*)&Bs[bk][bn + 4] =
            make_float4(to_tf32(pb1.x), to_tf32(pb1.y), to_tf32(pb1.z), to_tf32(pb1.w));
        __syncthreads();

        if (k0 + 16 < Kdim) {
            if (aptr) {
                pa0 = *(const float4*)(aptr + k0 + 16 + akh);
                pa1 = *(const float4*)(aptr + k0 + 16 + akh + 4);
            }
            pb0 = *(const float4*)(bptr + (size_t)(k0 + 16) * bstride);
            pb1 = *(const float4*)(bptr + (size_t)(k0 + 16) * bstride + 4);
        }

#pragma unroll
        for (int ks = 0; ks < 16; ks += 8) {
            unsigned a[2][4];
#pragma unroll
            for (int mi = 0; mi < 2; mi++) {
                int m0 = wm * 32 + mi * 16;
                a[mi][0] = __float_as_uint(As[m0 + g][ks + t]);
                a[mi][1] = __float_as_uint(As[m0 + g + 8][ks + t]);
                a[mi][2] = __float_as_uint(As[m0 + g][ks + t + 4]);
                a[mi][3] = __float_as_uint(As[m0 + g + 8][ks + t + 4]);
            }
#pragma unroll
            for (int ni = 0; ni < 8; ni++) {
                int n0 = wn * 64 + ni * 8;
                unsigned b[2];
                b[0] = __float_as_uint(Bs[ks + t][n0 + g]);
                b[1] = __float_as_uint(Bs[ks + t + 4][n0 + g]);
                mma_tf32(acc[0][ni], a[0], b);
                mma_tf32(acc[1][ni], a[1], b);
            }
        }
        __syncthreads();
    }

    // ------------------------------ epilogue ---------------------------------
    float* outbase = nullptr;
    if (MODE == 0) outbase = (e == 0) ? g_q : (e == 1) ? g_k : g_v;
#pragma unroll
    for (int mi = 0; mi < 2; mi++) {
#pragma unroll
        for (int rs = 0; rs < 2; rs++) {
            int m = mtile * 128 + wm * 32 + mi * 16 + g + rs * 8;
            int slot = 0; float gte = 0.f;
            bool valid = true;
            if (MODE >= 2) {
                if (m >= Mcount) valid = false;
                else {
                    slot = list[m];
                    if (MODE == 3) gte = g_gate[slot];
                }
            }
            if (!valid) continue;
#pragma unroll
            for (int ni = 0; ni < 8; ni++) {
                int n = ntile * 128 + wn * 64 + ni * 8 + 2 * t;
                float v0 = acc[mi][ni][rs * 2], v1 = acc[mi][ni][rs * 2 + 1];
                if (MODE == 0) {
                    int hh = n >> 6, d = n & 63;
                    float* op = outbase + ((size_t)hh * TT + m) * 64 + d;
                    *(float2*)op = make_float2(v0, v1);
                } else if (MODE == 1) {
                    size_t base = (size_t)m * CC + n;
                    float2 rv = *(const float2*)(resid + base);
                    *(float2*)(Cout + base) =
                        make_float2(v0 + bias[n] + rv.x, v1 + bias[n + 1] + rv.y);
                } else if (MODE == 2) {
                    float* op = g_Hbuf + (size_t)slot * FF + n;
                    *(float2*)op = make_float2(fmaxf(v0 + biasp[n], 0.f),
                                               fmaxf(v1 + biasp[n + 1], 0.f));
                } else {
                    float* op = g_O2 + (size_t)slot * CC + n;
                    *(float2*)op = make_float2(gte * (v0 + biasp[n]),
                                               gte * (v1 + biasp[n + 1]));
                }
            }
        }
    }
}

// ------------------------- Flash attention (causal, tf32 mma) ----------------
// Block: 128 threads (4 warps), 64 q-rows; Q held in REGISTERS (a-fragments).
// Static smem only: Ks[64][68] (aliased as P after softmax) + Vs[64][68] = 34.8KB.
__global__ __launch_bounds__(128)
void attn_kernel()
{
    __shared__ float Ks[64 * 68];   // K tile, later aliased as P
    __shared__ float Vs[64 * 68];   // V tile

    const int qt = gridDim.x - 1 - blockIdx.x;   // heavy tiles first
    const int h  = blockIdx.y;
    const int tid = threadIdx.x;
    const int wid = tid >> 5, lane = tid & 31;
    const int g = lane >> 2, t = lane & 3;
    const int m0 = wid * 16;
    const float scale = 0.03125f;  // C^-0.5

    // ---- stage Q through Ks once, extract a-fragments into registers ----
    const float* Qg = g_q + ((size_t)h * TT + qt * 64) * DD;
#pragma unroll
    for (int j = 0; j < 8; j++) {
        int idx = j * 512 + tid * 4;
        float4 v = *(const float4*)(Qg + idx);
        int r = idx >> 6, d = idx & 63;
        *(float4*)(Ks + r * 68 + d) =
            make_float4(to_tf32(v.x), to_tf32(v.y), to_tf32(v.z), to_tf32(v.w));
    }
    __syncthreads();
    unsigned qfrag[8][4];
#pragma unroll
    for (int ks = 0; ks < 8; ks++) {
        qfrag[ks][0] = __float_as_uint(Ks[(m0 + g) * 68 + ks * 8 + t]);
        qfrag[ks][1] = __float_as_uint(Ks[(m0 + g + 8) * 68 + ks * 8 + t]);
        qfrag[ks][2] = __float_as_uint(Ks[(m0 + g) * 68 + ks * 8 + t + 4]);
        qfrag[ks][3] = __float_as_uint(Ks[(m0 + g + 8) * 68 + ks * 8 + t + 4]);
    }

    float accO[8][4];
#pragma unroll
    for (int i = 0; i < 8; i++)
#pragma unroll
        for (int j = 0; j < 4; j++) accO[i][j] = 0.f;
    float mrow[2] = {-1e30f, -1e30f}, lrow[2] = {0.f, 0.f};

    for (int kt = 0; kt <= qt; kt++) {
        __syncthreads();   // prior use of Ks(P)/Vs complete (iter0: Q extraction)
        const float* Kg = g_k + ((size_t)h * TT + kt * 64) * DD;
        const float* Vg = g_v + ((size_t)h * TT + kt * 64) * DD;
#pragma unroll
        for (int j = 0; j < 8; j++) {
            int idx = j * 512 + tid * 4;
            int r = idx >> 6, d = idx & 63;
            float4 kv = *(const float4*)(Kg + idx);
            *(float4*)(Ks + r * 68 + d) =
                make_float4(to_tf32(kv.x), to_tf32(kv.y), to_tf32(kv.z), to_tf32(kv.w));
            float4 vv = *(const float4*)(Vg + idx);
            *(float4*)(Vs + r * 68 + d) =
                make_float4(to_tf32(vv.x), to_tf32(vv.y), to_tf32(vv.z), to_tf32(vv.w));
        }
        __syncthreads();

        // ---- S = Q @ K^T ----
        float sacc[8][4];
#pragma unroll
        for (int i = 0; i < 8; i++)
#pragma unroll
            for (int j = 0; j < 4; j++) sacc[i][j] = 0.f;
#pragma unroll
        for (int ks = 0; ks < 8; ks++) {
#pragma unroll
            for (int ni = 0; ni < 8; ni++) {
                unsigned b[2];
                b[0] = __float_as_uint(Ks[(ni * 8 + g) * 68 + ks * 8 + t]);
                b[1] = __float_as_uint(Ks[(ni * 8 + g) * 68 + ks * 8 + t + 4]);
                mma_tf32(sacc[ni], qfrag[ks], b);
            }
        }

        // ---- scale + causal mask + online softmax ----
#pragma unroll
        for (int r = 0; r < 2; r++) {
            int rowl = m0 + g + r * 8;
            float vmax = -1e30f;
#pragma unroll
            for (int ni = 0; ni < 8; ni++) {
                float s0 = sacc[ni][r * 2] * scale;
                float s1 = sacc[ni][r * 2 + 1] * scale;
                if (kt == qt) {
                    int c0 = ni * 8 + 2 * t;
                    if (c0 > rowl)     s0 = -1e30f;
                    if (c0 + 1 > rowl) s1 = -1e30f;
                }
                sacc[ni][r * 2] = s0; sacc[ni][r * 2 + 1] = s1;
                vmax = fmaxf(vmax, fmaxf(s0, s1));
            }
            vmax = fmaxf(vmax, __shfl_xor_sync(0xffffffffu, vmax, 1));
            vmax = fmaxf(vmax, __shfl_xor_sync(0xffffffffu, vmax, 2));
            float mn  = fmaxf(mrow[r], vmax);
            float fac = __expf(mrow[r] - mn);
            float sum = 0.f;
#pragma unroll
            for (int ni = 0; ni < 8; ni++) {
                float p0 = __expf(sacc[ni][r * 2] - mn);
                float p1 = __expf(sacc[ni][r * 2 + 1] - mn);
                sacc[ni][r * 2] = p0; sacc[ni][r * 2 + 1] = p1;
                sum += p0 + p1;
            }
            sum += __shfl_xor_sync(0xffffffffu, sum, 1);
            sum += __shfl_xor_sync(0xffffffffu, sum, 2);
            mrow[r] = mn;
            lrow[r] = lrow[r] * fac + sum;
#pragma unroll
            for (int ni = 0; ni < 8; ni++) {
                accO[ni][r * 2]     *= fac;
                accO[ni][r * 2 + 1] *= fac;
            }
        }

        __syncthreads();   // all warps done reading Ks as K
        float* Ps = Ks;    // alias
#pragma unroll
        for (int ni = 0; ni < 8; ni++) {
            Ps[(m0 + g) * 68 + ni * 8 + 2 * t]         = to_tf32(sacc[ni][0]);
            Ps[(m0 + g) * 68 + ni * 8 + 2 * t + 1]     = to_tf32(sacc[ni][1]);
            Ps[(m0 + g + 8) * 68 + ni * 8 + 2 * t]     = to_tf32(sacc[ni][2]);
            Ps[(m0 + g + 8) * 68 + ni * 8 + 2 * t + 1] = to_tf32(sacc[ni][3]);
        }
        __syncwarp();      // warp reads only its own 16 P-rows

        // ---- O += P @ V ----
#pragma unroll
        for (int ks = 0; ks < 8; ks++) {
            unsigned a[4];
            a[0] = __float_as_uint(Ps[(m0 + g) * 68 + ks * 8 + t]);
            a[1] = __float_as_uint(Ps[(m0 + g + 8) * 68 + ks * 8 + t]);
            a[2] = __float_as_uint(Ps[(m0 + g) * 68 + ks * 8 + t + 4]);
            a[3] = __float_as_uint(Ps[(m0 + g + 8) * 68 + ks * 8 + t + 4]);
#pragma unroll
            for (int ni = 0; ni < 8; ni++) {
                unsigned b[2];
                b[0] = __float_as_uint(Vs[(ks * 8 + t) * 68 + ni * 8 + g]);
                b[1] = __float_as_uint(Vs[(ks * 8 + t + 4) * 68 + ni * 8 + g]);
                mma_tf32(accO[ni], a, b);
            }
        }
    }

#pragma unroll
    for (int r = 0; r < 2; r++) {
        float inv = 1.f / lrow[r];
        int row = qt * 64 + m0 + g + r * 8;
#pragma unroll
        for (int ni = 0; ni < 8; ni++) {
            int col = h * 64 + ni * 8 + 2 * t;
            *(float2*)(g_att + (size_t)row * CC + col) =
                make_float2(accO[ni][r * 2] * inv, accO[ni][r * 2 + 1] * inv);
        }
    }
}

// ------------------------------ Router ---------------------------------------
__global__ void zero_counts_kernel() { if (threadIdx.x < EE) g_count[threadIdx.x] = 0; }

__global__ void router_kernel(const float* __restrict__ Wr, const float* __restrict__ br,
                              const float* __restrict__ Wn, const float* __restrict__ bn,
                              const float* __restrict__ noise)
{
    int t = blockIdx.x * 8 + (threadIdx.x >> 5);
    int lane = threadIdx.x & 31;
    const float* xr = g_xn2 + (size_t)t * CC;
    float ar[8] = {0,0,0,0,0,0,0,0}, an[8] = {0,0,0,0,0,0,0,0};
    for (int c = lane; c < CC; c += 32) {
        float xv = xr[c];
        float4 w0 = *(const float4*)(Wr + c * 8);
        float4 w1 = *(const float4*)(Wr + c * 8 + 4);
        ar[0] += xv * w0.x; ar[1] += xv * w0.y; ar[2] += xv * w0.z; ar[3] += xv * w0.w;
        ar[4] += xv * w1.x; ar[5] += xv * w1.y; ar[6] += xv * w1.z; ar[7] += xv * w1.w;
        float4 n0 = *(const float4*)(Wn + c * 8);
        float4 n1 = *(const float4*)(Wn + c * 8 + 4);
        an[0] += xv * n0.x; an[1] += xv * n0.y; an[2] += xv * n0.z; an[3] += xv * n0.w;
        an[4] += xv * n1.x; an[5] += xv * n1.y; an[6] += xv * n1.z; an[7] += xv * n1.w;
    }
#pragma unroll
    for (int e = 0; e < 8; e++) {
#pragma unroll
        for (int o = 16; o > 0; o >>= 1) {
            ar[e] += __shfl_xor_sync(0xffffffffu, ar[e], o);
            an[e] += __shfl_xor_sync(0xffffffffu, an[e], o);
        }
    }
    if (lane == 0) {
        float noisy[8];
#pragma unroll
        for (int e = 0; e < 8; e++) {
            float l  = ar[e] + br[e];
            float nl = an[e] + bn[e];
            float sp = (nl > 20.f) ? nl : log1pf(expf(nl));
            noisy[e] = l + noise[t * 8 + e] * sp;
        }
        int i1 = 0;
        for (int e = 1; e < 8; e++) if (noisy[e] > noisy[i1]) i1 = e;
        int i2 = (i1 == 0) ? 1 : 0;
        for (int e = 0; e < 8; e++)
            if (e != i1 && noisy[e] > noisy[i2]) i2 = e;
        float ee = expf(noisy[i2] - noisy[i1]);
        float z  = 1.f + ee;
        float g1 = 1.f / z, g2 = ee / z;
        int p1 = atomicAdd(&g_count[i1], 1);
        g_list[i1 * TT + p1] = t * 2;     g_gate[t * 2]     = g1;
        int p2 = atomicAdd(&g_count[i2], 1);
        g_list[i2 * TT + p2] = t * 2 + 1; g_gate[t * 2 + 1] = g2;
    }
}

// ------------------------------ Combine --------------------------------------
__global__ void combine_kernel(float* __restrict__ out)
{
    int t = blockIdx.x;
    size_t b0 = (size_t)(t * 2) * CC;
    size_t b1 = (size_t)(t * 2 + 1) * CC;
    for (int c = threadIdx.x; c < CC; c += 256)
        out[(size_t)t * CC + c] += g_O2[b0 + c] + g_O2[b1 + c];
}

// ------------------------------ launch ---------------------------------------
extern "C" void kernel_launch(void* const* d_in, const int* in_sizes, int n_in,
                              void* d_out, int out_size)
{
    (void)in_sizes; (void)n_in; (void)out_size;
    const float* x     = (const float*)d_in[0];
    const float* noise = (const float*)d_in[1];
    const float* ln1_g = (const float*)d_in[2];
    const float* ln1_b = (const float*)d_in[3];
    const float* ln2_g = (const float*)d_in[4];
    const float* ln2_b = (const float*)d_in[5];
    const float* Wq    = (const float*)d_in[6];
    const float* Wk    = (const float*)d_in[7];
    const float* Wv    = (const float*)d_in[8];
    const float* Wproj = (const float*)d_in[9];
    const float* bproj = (const float*)d_in[10];
    const float* Wr    = (const float*)d_in[11];
    const float* br    = (const float*)d_in[12];
    const float* Wn    = (const float*)d_in[13];
    const float* bn    = (const float*)d_in[14];
    const float* W1    = (const float*)d_in[15];
    const float* b1    = (const float*)d_in[16];
    const float* W2    = (const float*)d_in[17];
    const float* b2    = (const float*)d_in[18];
    float* out = (float*)d_out;

    ln_kernel<0><<<TT, 256>>>(x, ln1_g, ln1_b);

    // fused QKV: z = 0/1/2 selects Wq/Wk/Wv
    gemm_kernel<0><<<dim3(CC / 128, TT / 128, 3), 256>>>(
        Wq, Wk, Wv, nullptr, nullptr, nullptr, CC, CC);

    attn_kernel<<<dim3(TT / 64, HH), 128>>>();

    gemm_kernel<1><<<dim3(CC / 128, TT / 128), 256>>>(
        Wproj, nullptr, nullptr, bproj, x, out, CC, CC);

    ln_kernel<1><<<TT, 256>>>(out, ln2_g, ln2_b);

    zero_counts_kernel<<<1, 32>>>();
    router_kernel<<<TT / 8, 256>>>(Wr, br, Wn, bn, noise);

    gemm_kernel<2><<<dim3(FF / 128, 16, EE), 256>>>(
        W1, nullptr, nullptr, b1, nullptr, nullptr, CC, FF);
    gemm_kernel<3><<<dim3(CC / 128, 16, EE), 256>>>(
        W2, nullptr, nullptr, b2, nullptr, nullptr, FF, CC);

    combine_kernel<<<TT, 256>>>(out);
}

// round 9
// speedup vs baseline: 2.5095x; 1.0064x over previous
#include <cuda_runtime.h>
#include <math.h>

#define TT 2048
#define CC 1024
#define HH 16
#define DD 64
#define EE 8
#define FF 4096

// ------------------------- scratch (device globals; no allocs) ---------------
__device__ float g_xn  [TT * CC];          // LN1 output
__device__ float g_q   [HH * TT * DD];     // (H,T,D)
__device__ float g_k   [HH * TT * DD];
__device__ float g_v   [HH * TT * DD];
__device__ float g_att [TT * CC];          // concat-head attention output
__device__ float g_xn2 [TT * CC];          // LN2 output
__device__ float g_Hbuf[(size_t)TT * 2 * FF];  // expert hidden, slot-indexed
__device__ float g_O2  [(size_t)TT * 2 * CC];  // expert output * gate, slot-indexed
__device__ float g_gate[TT * 2];
__device__ int   g_list[EE * TT];
__device__ int   g_count[EE];

// ------------------------------ helpers --------------------------------------
__device__ __forceinline__ float to_tf32(float x) {
    float r;
    asm("cvt.rna.tf32.f32 %0, %1;" : "=f"(r) : "f"(x));
    return r;
}

__device__ __forceinline__ void mma_tf32(float* c, const unsigned* a, const unsigned* b) {
    asm volatile(
        "mma.sync.aligned.m16n8k8.row.col.f32.tf32.tf32.f32 "
        "{%0,%1,%2,%3}, {%4,%5,%6,%7}, {%8,%9}, {%0,%1,%2,%3};"
        : "+f"(c[0]), "+f"(c[1]), "+f"(c[2]), "+f"(c[3])
        : "r"(a[0]), "r"(a[1]), "r"(a[2]), "r"(a[3]), "r"(b[0]), "r"(b[1]));
}

// ------------------------------ LayerNorm ------------------------------------
template <int PHASE>
__global__ void ln_kernel(const float* __restrict__ x,
                          const float* __restrict__ gamma,
                          const float* __restrict__ beta)
{
    int t = blockIdx.x;
    const float* xr = x + (size_t)t * CC;
    float s = 0.f, s2 = 0.f;
    for (int c = threadIdx.x; c < CC; c += 256) {
        float v = xr[c]; s += v; s2 += v * v;
    }
#pragma unroll
    for (int o = 16; o > 0; o >>= 1) {
        s  += __shfl_xor_sync(0xffffffffu, s,  o);
        s2 += __shfl_xor_sync(0xffffffffu, s2, o);
    }
    __shared__ float sm[8], sm2[8];
    __shared__ float smean, srstd;
    if ((threadIdx.x & 31) == 0) { sm[threadIdx.x >> 5] = s; sm2[threadIdx.x >> 5] = s2; }
    __syncthreads();
    if (threadIdx.x == 0) {
        float a = 0.f, a2 = 0.f;
        for (int i = 0; i < 8; i++) { a += sm[i]; a2 += sm2[i]; }
        float m   = a * (1.f / CC);
        float var = a2 * (1.f / CC) - m * m;
        smean = m; srstd = rsqrtf(var + 1e-5f);
    }
    __syncthreads();
    float m = smean, r = srstd;
    float* out = (PHASE == 0) ? g_xn : g_xn2;
    for (int c = threadIdx.x; c < CC; c += 256)
        out[(size_t)t * CC + c] = (xr[c] - m) * r * gamma[c] + beta[c];
}

// ------------------------------ tensor-core GEMM -----------------------------
// Tile 128x128, BK=16, 256 threads (8 warps), warp tile 32x64 via m16n8k8 tf32.
// MODE 0: QKV fused  A=g_xn  B in {Wq,Wk,Wv} by blockIdx.z     out (H,T,D)
// MODE 1: proj       A=g_att B=Wproj (C,C)                     out = acc+bias+resid
// MODE 2: FFN1       A=g_xn2 gathered  B=W1[e] (C,F)           relu -> g_Hbuf[slot]
// MODE 3: FFN2       A=g_Hbuf gathered B=W2[e] (F,C)           gate*(..) -> g_O2[slot]
template <int MODE>
__global__ __launch_bounds__(256, 2)
void gemm_kernel(const float* __restrict__ B,
                 const float* __restrict__ B2,
                 const float* __restrict__ B3,
                 const float* __restrict__ bias,
                 const float* __restrict__ resid,
                 float* __restrict__ Cout,
                 int Kdim, int Ndim)
{
    const int tid = threadIdx.x;
    const int mtile = blockIdx.y, ntile = blockIdx.x;
    const int e = blockIdx.z;   // expert (MODE>=2) or qkv-select (MODE 0)

    int Mcount = TT;
    const int* list = nullptr;
    const float* Bp = B;
    const float* biasp = bias;
    if (MODE == 0) {
        Bp = (e == 0) ? B : (e == 1) ? B2 : B3;
    } else if (MODE >= 2) {
        Mcount = g_count[e];
        if (mtile * 128 >= Mcount) return;
        list  = g_list + e * TT;
        Bp    = B + (size_t)e * Kdim * Ndim;
        biasp = bias + (size_t)e * Ndim;
    }

    __shared__ float As[128][20];    // [m][k]
    __shared__ float Bs[16][136];    // [k][n], stride 136 (mod 32 = 8, conflict-free frags)

    const int wid = tid >> 5, lane = tid & 31;
    const int wm = wid & 3, wn = wid >> 2;   // warp grid: 4 (M) x 2 (N)
    const int g = lane >> 2, t = lane & 3;

    // A global loading: 2 threads per row, 8 floats each
    const int arow = tid >> 1;
    const int akh  = (tid & 1) * 8;
    const float* aptr = nullptr;
    {
        int r = mtile * 128 + arow;
        if (MODE == 0)      aptr = g_xn  + (size_t)r * CC;
        else if (MODE == 1) aptr = g_att + (size_t)r * CC;
        else if (r < Mcount) {
            int slot = list[r];
            aptr = (MODE == 2) ? (g_xn2  + (size_t)(slot >> 1) * CC)
                               : (g_Hbuf + (size_t)slot * FF);
        }
    }
    // B global loading: row k = tid>>4, 8 cols
    const int bk = tid >> 4;
    const int bn = (tid & 15) * 8;
    const float* bptr;
    size_t bstride;
    if (MODE == 0) {
        int n = ntile * 128 + bn;
        int hh = n >> 6, d = n & 63;
        bptr = Bp + ((size_t)hh * Kdim + bk) * 64 + d;
        bstride = 64;
    } else {
        bptr = Bp + (size_t)bk * Ndim + ntile * 128 + bn;
        bstride = (size_t)Ndim;
    }

    float4 pa0, pa1, pb0, pb1;
    if (aptr) { pa0 = *(const float4*)(aptr + akh); pa1 = *(const float4*)(aptr + akh + 4); }
    else      { pa0 = make_float4(0.f, 0.f, 0.f, 0.f); pa1 = pa0; }
    pb0 = *(const float4*)(bptr);
    pb1 = *(const float4*)(bptr + 4);

    float acc[2][8][4];
#pragma unroll
    for (int i = 0; i < 2; i++)
#pragma unroll
        for (int j = 0; j < 8; j++)
#pragma unroll
            for (int q = 0; q < 4; q++) acc[i][j][q] = 0.f;

    for (int k0 = 0; k0 < Kdim; k0 += 16) {
        *(float4*)&As[arow][akh] =
            make_float4(to_tf32(pa0.x), to_tf32(pa0.y), to_tf32(pa0.z), to_tf32(pa0.w));
        *(float4*)&As[arow][akh + 4] =
            make_float4(to_tf32(pa1.x), to_tf32(pa1.y), to_tf32(pa1.z), to_tf32(pa1.w));
        *(float4*)&Bs[bk][bn] =
            make_float4(to_tf32(pb0.x), to_tf32(pb0.y), to_tf32(pb0.z), to_tf32(pb0.w));
        *(float4*)&Bs[bk][bn + 4] =
            make_float4(to_tf32(pb1.x), to_tf32(pb1.y), to_tf32(pb1.z), to_tf32(pb1.w));
        __syncthreads();

        if (k0 + 16 < Kdim) {
            if (aptr) {
                pa0 = *(const float4*)(aptr + k0 + 16 + akh);
                pa1 = *(const float4*)(aptr + k0 + 16 + akh + 4);
            }
            pb0 = *(const float4*)(bptr + (size_t)(k0 + 16) * bstride);
            pb1 = *(const float4*)(bptr + (size_t)(k0 + 16) * bstride + 4);
        }

#pragma unroll
        for (int ks = 0; ks < 16; ks += 8) {
            unsigned a[2][4];
#pragma unroll
            for (int mi = 0; mi < 2; mi++) {
                int m0 = wm * 32 + mi * 16;
                a[mi][0] = __float_as_uint(As[m0 + g][ks + t]);
                a[mi][1] = __float_as_uint(As[m0 + g + 8][ks + t]);
                a[mi][2] = __float_as_uint(As[m0 + g][ks + t + 4]);
                a[mi][3] = __float_as_uint(As[m0 + g + 8][ks + t + 4]);
            }
#pragma unroll
            for (int ni = 0; ni < 8; ni++) {
                int n0 = wn * 64 + ni * 8;
                unsigned b[2];
                b[0] = __float_as_uint(Bs[ks + t][n0 + g]);
                b[1] = __float_as_uint(Bs[ks + t + 4][n0 + g]);
                mma_tf32(acc[0][ni], a[0], b);
                mma_tf32(acc[1][ni], a[1], b);
            }
        }
        __syncthreads();
    }

    // ------------------------------ epilogue ---------------------------------
    float* outbase = nullptr;
    if (MODE == 0) outbase = (e == 0) ? g_q : (e == 1) ? g_k : g_v;
#pragma unroll
    for (int mi = 0; mi < 2; mi++) {
#pragma unroll
        for (int rs = 0; rs < 2; rs++) {
            int m = mtile * 128 + wm * 32 + mi * 16 + g + rs * 8;
            int slot = 0; float gte = 0.f;
            bool valid = true;
            if (MODE >= 2) {
                if (m >= Mcount) valid = false;
                else {
                    slot = list[m];
                    if (MODE == 3) gte = g_gate[slot];
                }
            }
            if (!valid) continue;
#pragma unroll
            for (int ni = 0; ni < 8; ni++) {
                int n = ntile * 128 + wn * 64 + ni * 8 + 2 * t;
                float v0 = acc[mi][ni][rs * 2], v1 = acc[mi][ni][rs * 2 + 1];
                if (MODE == 0) {
                    int hh = n >> 6, d = n & 63;
                    float* op = outbase + ((size_t)hh * TT + m) * 64 + d;
                    *(float2*)op = make_float2(v0, v1);
                } else if (MODE == 1) {
                    size_t base = (size_t)m * CC + n;
                    float2 rv = *(const float2*)(resid + base);
                    *(float2*)(Cout + base) =
                        make_float2(v0 + bias[n] + rv.x, v1 + bias[n + 1] + rv.y);
                } else if (MODE == 2) {
                    float* op = g_Hbuf + (size_t)slot * FF + n;
                    *(float2*)op = make_float2(fmaxf(v0 + biasp[n], 0.f),
                                               fmaxf(v1 + biasp[n + 1], 0.f));
                } else {
                    float* op = g_O2 + (size_t)slot * CC + n;
                    *(float2*)op = make_float2(gte * (v0 + biasp[n]),
                                               gte * (v1 + biasp[n + 1]));
                }
            }
        }
    }
}

// ------------------------- Flash attention (causal, tf32 mma) ----------------
// Block: 128 threads (4 warps), 64 q-rows; Q held in REGISTERS (a-fragments).
// Static smem only: Ks[64][68] (aliased as P after softmax) + Vs[64][68] = 34.8KB.
__global__ __launch_bounds__(128, 3)
void attn_kernel()
{
    __shared__ float Ks[64 * 68];   // K tile, later aliased as P
    __shared__ float Vs[64 * 68];   // V tile

    const int qt = gridDim.x - 1 - blockIdx.x;   // heavy tiles first
    const int h  = blockIdx.y;
    const int tid = threadIdx.x;
    const int wid = tid >> 5, lane = tid & 31;
    const int g = lane >> 2, t = lane & 3;
    const int m0 = wid * 16;
    const float scale = 0.03125f;  // C^-0.5

    // ---- stage Q through Ks once, extract a-fragments into registers ----
    const float* Qg = g_q + ((size_t)h * TT + qt * 64) * DD;
#pragma unroll
    for (int j = 0; j < 8; j++) {
        int idx = j * 512 + tid * 4;
        float4 v = *(const float4*)(Qg + idx);
        int r = idx >> 6, d = idx & 63;
        *(float4*)(Ks + r * 68 + d) =
            make_float4(to_tf32(v.x), to_tf32(v.y), to_tf32(v.z), to_tf32(v.w));
    }
    __syncthreads();
    unsigned qfrag[8][4];
#pragma unroll
    for (int ks = 0; ks < 8; ks++) {
        qfrag[ks][0] = __float_as_uint(Ks[(m0 + g) * 68 + ks * 8 + t]);
        qfrag[ks][1] = __float_as_uint(Ks[(m0 + g + 8) * 68 + ks * 8 + t]);
        qfrag[ks][2] = __float_as_uint(Ks[(m0 + g) * 68 + ks * 8 + t + 4]);
        qfrag[ks][3] = __float_as_uint(Ks[(m0 + g + 8) * 68 + ks * 8 + t + 4]);
    }

    float accO[8][4];
#pragma unroll
    for (int i = 0; i < 8; i++)
#pragma unroll
        for (int j = 0; j < 4; j++) accO[i][j] = 0.f;
    float mrow[2] = {-1e30f, -1e30f}, lrow[2] = {0.f, 0.f};

    for (int kt = 0; kt <= qt; kt++) {
        __syncthreads();   // prior use of Ks(P)/Vs complete (iter0: Q extraction)
        const float* Kg = g_k + ((size_t)h * TT + kt * 64) * DD;
        const float* Vg = g_v + ((size_t)h * TT + kt * 64) * DD;
#pragma unroll
        for (int j = 0; j < 8; j++) {
            int idx = j * 512 + tid * 4;
            int r = idx >> 6, d = idx & 63;
            float4 kv = *(const float4*)(Kg + idx);
            *(float4*)(Ks + r * 68 + d) =
                make_float4(to_tf32(kv.x), to_tf32(kv.y), to_tf32(kv.z), to_tf32(kv.w));
            float4 vv = *(const float4*)(Vg + idx);
            *(float4*)(Vs + r * 68 + d) =
                make_float4(to_tf32(vv.x), to_tf32(vv.y), to_tf32(vv.z), to_tf32(vv.w));
        }
        __syncthreads();

        // ---- S = Q @ K^T ----
        float sacc[8][4];
#pragma unroll
        for (int i = 0; i < 8; i++)
#pragma unroll
            for (int j = 0; j < 4; j++) sacc[i][j] = 0.f;
#pragma unroll
        for (int ks = 0; ks < 8; ks++) {
#pragma unroll
            for (int ni = 0; ni < 8; ni++) {
                unsigned b[2];
                b[0] = __float_as_uint(Ks[(ni * 8 + g) * 68 + ks * 8 + t]);
                b[1] = __float_as_uint(Ks[(ni * 8 + g) * 68 + ks * 8 + t + 4]);
                mma_tf32(sacc[ni], qfrag[ks], b);
            }
        }

        // ---- scale + causal mask + online softmax ----
#pragma unroll
        for (int r = 0; r < 2; r++) {
            int rowl = m0 + g + r * 8;
            float vmax = -1e30f;
#pragma unroll
            for (int ni = 0; ni < 8; ni++) {
                float s0 = sacc[ni][r * 2] * scale;
                float s1 = sacc[ni][r * 2 + 1] * scale;
                if (kt == qt) {
                    int c0 = ni * 8 + 2 * t;
                    if (c0 > rowl)     s0 = -1e30f;
                    if (c0 + 1 > rowl) s1 = -1e30f;
                }
                sacc[ni][r * 2] = s0; sacc[ni][r * 2 + 1] = s1;
                vmax = fmaxf(vmax, fmaxf(s0, s1));
            }
            vmax = fmaxf(vmax, __shfl_xor_sync(0xffffffffu, vmax, 1));
            vmax = fmaxf(vmax, __shfl_xor_sync(0xffffffffu, vmax, 2));
            float mn  = fmaxf(mrow[r], vmax);
            float fac = __expf(mrow[r] - mn);
            float sum = 0.f;
#pragma unroll
            for (int ni = 0; ni < 8; ni++) {
                float p0 = __expf(sacc[ni][r * 2] - mn);
                float p1 = __expf(sacc[ni][r * 2 + 1] - mn);
                sacc[ni][r * 2] = p0; sacc[ni][r * 2 + 1] = p1;
                sum += p0 + p1;
            }
            sum += __shfl_xor_sync(0xffffffffu, sum, 1);
            sum += __shfl_xor_sync(0xffffffffu, sum, 2);
            mrow[r] = mn;
            lrow[r] = lrow[r] * fac + sum;
#pragma unroll
            for (int ni = 0; ni < 8; ni++) {
                accO[ni][r * 2]     *= fac;
                accO[ni][r * 2 + 1] *= fac;
            }
        }

        __syncthreads();   // all warps done reading Ks as K
        float* Ps = Ks;    // alias
#pragma unroll
        for (int ni = 0; ni < 8; ni++) {
            Ps[(m0 + g) * 68 + ni * 8 + 2 * t]         = to_tf32(sacc[ni][0]);
            Ps[(m0 + g) * 68 + ni * 8 + 2 * t + 1]     = to_tf32(sacc[ni][1]);
            Ps[(m0 + g + 8) * 68 + ni * 8 + 2 * t]     = to_tf32(sacc[ni][2]);
            Ps[(m0 + g + 8) * 68 + ni * 8 + 2 * t + 1] = to_tf32(sacc[ni][3]);
        }
        __syncwarp();      // warp reads only its own 16 P-rows

        // ---- O += P @ V ----
#pragma unroll
        for (int ks = 0; ks < 8; ks++) {
            unsigned a[4];
            a[0] = __float_as_uint(Ps[(m0 + g) * 68 + ks * 8 + t]);
            a[1] = __float_as_uint(Ps[(m0 + g + 8) * 68 + ks * 8 + t]);
            a[2] = __float_as_uint(Ps[(m0 + g) * 68 + ks * 8 + t + 4]);
            a[3] = __float_as_uint(Ps[(m0 + g + 8) * 68 + ks * 8 + t + 4]);
#pragma unroll
            for (int ni = 0; ni < 8; ni++) {
                unsigned b[2];
                b[0] = __float_as_uint(Vs[(ks * 8 + t) * 68 + ni * 8 + g]);
                b[1] = __float_as_uint(Vs[(ks * 8 + t + 4) * 68 + ni * 8 + g]);
                mma_tf32(accO[ni], a, b);
            }
        }
    }

#pragma unroll
    for (int r = 0; r < 2; r++) {
        float inv = 1.f / lrow[r];
        int row = qt * 64 + m0 + g + r * 8;
#pragma unroll
        for (int ni = 0; ni < 8; ni++) {
            int col = h * 64 + ni * 8 + 2 * t;
            *(float2*)(g_att + (size_t)row * CC + col) =
                make_float2(accO[ni][r * 2] * inv, accO[ni][r * 2 + 1] * inv);
        }
    }
}

// ------------------------------ Router ---------------------------------------
__global__ void zero_counts_kernel() { if (threadIdx.x < EE) g_count[threadIdx.x] = 0; }

__global__ void router_kernel(const float* __restrict__ Wr, const float* __restrict__ br,
                              const float* __restrict__ Wn, const float* __restrict__ bn,
                              const float* __restrict__ noise)
{
    int t = blockIdx.x * 8 + (threadIdx.x >> 5);
    int lane = threadIdx.x & 31;
    const float* xr = g_xn2 + (size_t)t * CC;
    float ar[8] = {0,0,0,0,0,0,0,0}, an[8] = {0,0,0,0,0,0,0,0};
    for (int c = lane; c < CC; c += 32) {
        float xv = xr[c];
        float4 w0 = *(const float4*)(Wr + c * 8);
        float4 w1 = *(const float4*)(Wr + c * 8 + 4);
        ar[0] += xv * w0.x; ar[1] += xv * w0.y; ar[2] += xv * w0.z; ar[3] += xv * w0.w;
        ar[4] += xv * w1.x; ar[5] += xv * w1.y; ar[6] += xv * w1.z; ar[7] += xv * w1.w;
        float4 n0 = *(const float4*)(Wn + c * 8);
        float4 n1 = *(const float4*)(Wn + c * 8 + 4);
        an[0] += xv * n0.x; an[1] += xv * n0.y; an[2] += xv * n0.z; an[3] += xv * n0.w;
        an[4] += xv * n1.x; an[5] += xv * n1.y; an[6] += xv * n1.z; an[7] += xv * n1.w;
    }
#pragma unroll
    for (int e = 0; e < 8; e++) {
#pragma unroll
        for (int o = 16; o > 0; o >>= 1) {
            ar[e] += __shfl_xor_sync(0xffffffffu, ar[e], o);
            an[e] += __shfl_xor_sync(0xffffffffu, an[e], o);
        }
    }
    if (lane == 0) {
        float noisy[8];
#pragma unroll
        for (int e = 0; e < 8; e++) {
            float l  = ar[e] + br[e];
            float nl = an[e] + bn[e];
            float sp = (nl > 20.f) ? nl : log1pf(expf(nl));
            noisy[e] = l + noise[t * 8 + e] * sp;
        }
        int i1 = 0;
        for (int e = 1; e < 8; e++) if (noisy[e] > noisy[i1]) i1 = e;
        int i2 = (i1 == 0) ? 1 : 0;
        for (int e = 0; e < 8; e++)
            if (e != i1 && noisy[e] > noisy[i2]) i2 = e;
        float ee = expf(noisy[i2] - noisy[i1]);
        float z  = 1.f + ee;
        float g1 = 1.f / z, g2 = ee / z;
        int p1 = atomicAdd(&g_count[i1], 1);
        g_list[i1 * TT + p1] = t * 2;     g_gate[t * 2]     = g1;
        int p2 = atomicAdd(&g_count[i2], 1);
        g_list[i2 * TT + p2] = t * 2 + 1; g_gate[t * 2 + 1] = g2;
    }
}

// ------------------------------ Combine --------------------------------------
__global__ void combine_kernel(float* __restrict__ out)
{
    int t = blockIdx.x;
    size_t b0 = (size_t)(t * 2) * CC;
    size_t b1 = (size_t)(t * 2 + 1) * CC;
    for (int c = threadIdx.x; c < CC; c += 256)
        out[(size_t)t * CC + c] += g_O2[b0 + c] + g_O2[b1 + c];
}

// ------------------------------ launch ---------------------------------------
extern "C" void kernel_launch(void* const* d_in, const int* in_sizes, int n_in,
                              void* d_out, int out_size)
{
    (void)in_sizes; (void)n_in; (void)out_size;
    const float* x     = (const float*)d_in[0];
    const float* noise = (const float*)d_in[1];
    const float* ln1_g = (const float*)d_in[2];
    const float* ln1_b = (const float*)d_in[3];
    const float* ln2_g = (const float*)d_in[4];
    const float* ln2_b = (const float*)d_in[5];
    const float* Wq    = (const float*)d_in[6];
    const float* Wk    = (const float*)d_in[7];
    const float* Wv    = (const float*)d_in[8];
    const float* Wproj = (const float*)d_in[9];
    const float* bproj = (const float*)d_in[10];
    const float* Wr    = (const float*)d_in[11];
    const float* br    = (const float*)d_in[12];
    const float* Wn    = (const float*)d_in[13];
    const float* bn    = (const float*)d_in[14];
    const float* W1    = (const float*)d_in[15];
    const float* b1    = (const float*)d_in[16];
    const float* W2    = (const float*)d_in[17];
    const float* b2    = (const float*)d_in[18];
    float* out = (float*)d_out;

    ln_kernel<0><<<TT, 256>>>(x, ln1_g, ln1_b);

    // fused QKV: z = 0/1/2 selects Wq/Wk/Wv
    gemm_kernel<0><<<dim3(CC / 128, TT / 128, 3), 256>>>(
        Wq, Wk, Wv, nullptr, nullptr, nullptr, CC, CC);

    attn_kernel<<<dim3(TT / 64, HH), 128>>>();

    gemm_kernel<1><<<dim3(CC / 128, TT / 128), 256>>>(
        Wproj, nullptr, nullptr, bproj, x, out, CC, CC);

    ln_kernel<1><<<TT, 256>>>(out, ln2_g, ln2_b);

    zero_counts_kernel<<<1, 32>>>();
    router_kernel<<<TT / 8, 256>>>(Wr, br, Wn, bn, noise);

    gemm_kernel<2><<<dim3(FF / 128, 16, EE), 256>>>(
        W1, nullptr, nullptr, b1, nullptr, nullptr, CC, FF);
    gemm_kernel<3><<<dim3(CC / 128, 16, EE), 256>>>(
        W2, nullptr, nullptr, b2, nullptr, nullptr, FF, CC);

    combine_kernel<<<TT, 256>>>(out);
}

// round 12
// speedup vs baseline: 3.0768x; 1.2261x over previous
#include <cuda_runtime.h>
#include <cuda_fp16.h>
#include <math.h>

#define TT 2048
#define CC 1024
#define HH 16
#define DD 64
#define EE 8
#define FF 4096

// ------------------------- scratch (device globals; no allocs) ---------------
__device__ float g_xn  [TT * CC];          // LN1 output
__device__ float g_q   [HH * TT * DD];     // (H,T,D)
__device__ float g_k   [HH * TT * DD];
__device__ float g_v   [HH * TT * DD];
__device__ float g_att [TT * CC];          // concat-head attention output
__device__ float g_xn2 [TT * CC];          // LN2 output
__device__ __half g_Hbuf[(size_t)TT * 2 * FF]; // expert hidden (fp16), slot-indexed
__device__ float g_O2  [(size_t)TT * 2 * CC];  // expert output * gate, slot-indexed
__device__ float g_gate[TT * 2];
__device__ int   g_list[EE * TT];
__device__ int   g_count[EE];

// fp16 transposed expert weights: stored [n][k] (k contiguous)
__device__ __half h_W1[(size_t)EE * FF * CC]; // per e: [n=F][k=C]
__device__ __half h_W2[(size_t)EE * CC * FF]; // per e: [n=C][k=F]

// ------------------------------ helpers --------------------------------------
__device__ __forceinline__ float to_tf32(float x) {
    float r;
    asm("cvt.rna.tf32.f32 %0, %1;" : "=f"(r) : "f"(x));
    return r;
}

__device__ __forceinline__ void mma_tf32(float* c, const unsigned* a, const unsigned* b) {
    asm volatile(
        "mma.sync.aligned.m16n8k8.row.col.f32.tf32.tf32.f32 "
        "{%0,%1,%2,%3}, {%4,%5,%6,%7}, {%8,%9}, {%0,%1,%2,%3};"
        : "+f"(c[0]), "+f"(c[1]), "+f"(c[2]), "+f"(c[3])
        : "r"(a[0]), "r"(a[1]), "r"(a[2]), "r"(a[3]), "r"(b[0]), "r"(b[1]));
}

__device__ __forceinline__ void mma_f16(float* c, const unsigned* a,
                                        unsigned b0, unsigned b1) {
    asm volatile(
        "mma.sync.aligned.m16n8k16.row.col.f32.f16.f16.f32 "
        "{%0,%1,%2,%3}, {%4,%5,%6,%7}, {%8,%9}, {%0,%1,%2,%3};"
        : "+f"(c[0]), "+f"(c[1]), "+f"(c[2]), "+f"(c[3])
        : "r"(a[0]), "r"(a[1]), "r"(a[2]), "r"(a[3]), "r"(b0), "r"(b1));
}

__device__ __forceinline__ unsigned packh2(float x, float y) {
    __half2 h = __floats2half2_rn(x, y);
    return *(unsigned*)&h;
}

// --------------------- weight transpose+convert (fp32 -> fp16 [n][k]) --------
// src [rows][cols] row-major fp32 -> dst [cols][rows] fp16. blockIdx.z = batch.
__global__ void transpose_h_kernel(const float* __restrict__ src,
                                   __half* __restrict__ dst,
                                   int rows, int cols,
                                   size_t sstride, size_t dstride)
{
    __shared__ __half tile[32][33];
    const size_t b = blockIdx.z;
    const int c0 = blockIdx.x * 32, r0 = blockIdx.y * 32;
    const int tx = threadIdx.x, ty = threadIdx.y;
#pragma unroll
    for (int i = 0; i < 4; i++) {
        int r = r0 + ty + i * 8;
        tile[ty + i * 8][tx] =
            __float2half(src[b * sstride + (size_t)r * cols + c0 + tx]);
    }
    __syncthreads();
#pragma unroll
    for (int i = 0; i < 4; i++) {
        int c = c0 + ty + i * 8;
        dst[b * dstride + (size_t)c * rows + r0 + tx] = tile[tx][ty + i * 8];
    }
}

// ------------------------------ LayerNorm ------------------------------------
template <int PHASE>
__global__ void ln_kernel(const float* __restrict__ x,
                          const float* __restrict__ gamma,
                          const float* __restrict__ beta)
{
    int t = blockIdx.x;
    const float* xr = x + (size_t)t * CC;
    float s = 0.f, s2 = 0.f;
    for (int c = threadIdx.x; c < CC; c += 256) {
        float v = xr[c]; s += v; s2 += v * v;
    }
#pragma unroll
    for (int o = 16; o > 0; o >>= 1) {
        s  += __shfl_xor_sync(0xffffffffu, s,  o);
        s2 += __shfl_xor_sync(0xffffffffu, s2, o);
    }
    __shared__ float sm[8], sm2[8];
    __shared__ float smean, srstd;
    if ((threadIdx.x & 31) == 0) { sm[threadIdx.x >> 5] = s; sm2[threadIdx.x >> 5] = s2; }
    __syncthreads();
    if (threadIdx.x == 0) {
        float a = 0.f, a2 = 0.f;
        for (int i = 0; i < 8; i++) { a += sm[i]; a2 += sm2[i]; }
        float m   = a * (1.f / CC);
        float var = a2 * (1.f / CC) - m * m;
        smean = m; srstd = rsqrtf(var + 1e-5f);
    }
    __syncthreads();
    float m = smean, r = srstd;
    float* out = (PHASE == 0) ? g_xn : g_xn2;
    for (int c = threadIdx.x; c < CC; c += 256)
        out[(size_t)t * CC + c] = (xr[c] - m) * r * gamma[c] + beta[c];
}

// ------------------------- tf32 GEMM (router-upstream path) ------------------
// Proven round-9 kernel. Tile 128x128, BK=16, 256 threads, m16n8k8 tf32.
// MODE 0: QKV fused  A=g_xn  B in {Wq,Wk,Wv} by blockIdx.z     out (H,T,D)
// MODE 1: proj       A=g_att B=Wproj (C,C)                     out = acc+bias+resid
template <int MODE>
__global__ __launch_bounds__(256, 2)
void gemm_kernel(const float* __restrict__ B,
                 const float* __restrict__ B2,
                 const float* __restrict__ B3,
                 const float* __restrict__ bias,
                 const float* __restrict__ resid,
                 float* __restrict__ Cout,
                 int Kdim, int Ndim)
{
    const int tid = threadIdx.x;
    const int mtile = blockIdx.y, ntile = blockIdx.x;
    const int e = blockIdx.z;

    const float* Bp = B;
    if (MODE == 0) Bp = (e == 0) ? B : (e == 1) ? B2 : B3;

    __shared__ float As[128][20];
    __shared__ float Bs[16][136];

    const int wid = tid >> 5, lane = tid & 31;
    const int wm = wid & 3, wn = wid >> 2;
    const int g = lane >> 2, t = lane & 3;

    const int arow = tid >> 1;
    const int akh  = (tid & 1) * 8;
    const float* aptr;
    {
        int r = mtile * 128 + arow;
        aptr = (MODE == 0) ? (g_xn + (size_t)r * CC) : (g_att + (size_t)r * CC);
    }
    const int bk = tid >> 4;
    const int bn = (tid & 15) * 8;
    const float* bptr;
    size_t bstride;
    if (MODE == 0) {
        int n = ntile * 128 + bn;
        int hh = n >> 6, d = n & 63;
        bptr = Bp + ((size_t)hh * Kdim + bk) * 64 + d;
        bstride = 64;
    } else {
        bptr = Bp + (size_t)bk * Ndim + ntile * 128 + bn;
        bstride = (size_t)Ndim;
    }

    float4 pa0, pa1, pb0, pb1;
    pa0 = *(const float4*)(aptr + akh);
    pa1 = *(const float4*)(aptr + akh + 4);
    pb0 = *(const float4*)(bptr);
    pb1 = *(const float4*)(bptr + 4);

    float acc[2][8][4];
#pragma unroll
    for (int i = 0; i < 2; i++)
#pragma unroll
        for (int j = 0; j < 8; j++)
#pragma unroll
            for (int q = 0; q < 4; q++) acc[i][j][q] = 0.f;

    for (int k0 = 0; k0 < Kdim; k0 += 16) {
        *(float4*)&As[arow][akh] =
            make_float4(to_tf32(pa0.x), to_tf32(pa0.y), to_tf32(pa0.z), to_tf32(pa0.w));
        *(float4*)&As[arow][akh + 4] =
            make_float4(to_tf32(pa1.x), to_tf32(pa1.y), to_tf32(pa1.z), to_tf32(pa1.w));
        *(float4*)&Bs[bk][bn] =
            make_float4(to_tf32(pb0.x), to_tf32(pb0.y), to_tf32(pb0.z), to_tf32(pb0.w));
        *(float4*)&Bs[bk][bn + 4] =
            make_float4(to_tf32(pb1.x), to_tf32(pb1.y), to_tf32(pb1.z), to_tf32(pb1.w));
        __syncthreads();

        if (k0 + 16 < Kdim) {
            pa0 = *(const float4*)(aptr + k0 + 16 + akh);
            pa1 = *(const float4*)(aptr + k0 + 16 + akh + 4);
            pb0 = *(const float4*)(bptr + (size_t)(k0 + 16) * bstride);
            pb1 = *(const float4*)(bptr + (size_t)(k0 + 16) * bstride + 4);
        }

#pragma unroll
        for (int ks = 0; ks < 16; ks += 8) {
            unsigned a[2][4];
#pragma unroll
            for (int mi = 0; mi < 2; mi++) {
                int m0 = wm * 32 + mi * 16;
                a[mi][0] = __float_as_uint(As[m0 + g][ks + t]);
                a[mi][1] = __float_as_uint(As[m0 + g + 8][ks + t]);
                a[mi][2] = __float_as_uint(As[m0 + g][ks + t + 4]);
                a[mi][3] = __float_as_uint(As[m0 + g + 8][ks + t + 4]);
            }
#pragma unroll
            for (int ni = 0; ni < 8; ni++) {
                int n0 = wn * 64 + ni * 8;
                unsigned b[2];
                b[0] = __float_as_uint(Bs[ks + t][n0 + g]);
                b[1] = __float_as_uint(Bs[ks + t + 4][n0 + g]);
                mma_tf32(acc[0][ni], a[0], b);
                mma_tf32(acc[1][ni], a[1], b);
            }
        }
        __syncthreads();
    }

#pragma unroll
    for (int mi = 0; mi < 2; mi++) {
#pragma unroll
        for (int rs = 0; rs < 2; rs++) {
            int m = mtile * 128 + wm * 32 + mi * 16 + g + rs * 8;
#pragma unroll
            for (int ni = 0; ni < 8; ni++) {
                int n = ntile * 128 + wn * 64 + ni * 8 + 2 * t;
                float v0 = acc[mi][ni][rs * 2], v1 = acc[mi][ni][rs * 2 + 1];
                if (MODE == 0) {
                    float* outbase = (e == 0) ? g_q : (e == 1) ? g_k : g_v;
                    int hh = n >> 6, d = n & 63;
                    float* op = outbase + ((size_t)hh * TT + m) * 64 + d;
                    *(float2*)op = make_float2(v0, v1);
                } else {
                    size_t base = (size_t)m * CC + n;
                    float2 rv = *(const float2*)(resid + base);
                    *(float2*)(Cout + base) =
                        make_float2(v0 + bias[n] + rv.x, v1 + bias[n + 1] + rv.y);
                }
            }
        }
    }
}

// ------------------- fp16 GEMM (expert FFN, router-downstream) ---------------
// Tile 128x128, BK=32, 256 threads, m16n8k16 f16/fp32-acc. B pre-transposed
// fp16 [n][k]. MODE 2: FFN1 gathered, relu -> g_Hbuf (fp16).
// MODE 3: FFN2 gathered (A fp16 in g_Hbuf), gate*(acc+bias) -> g_O2.
template <int MODE>
__global__ __launch_bounds__(256, 2)
void gemm_h_kernel(const float* __restrict__ bias, int Kdim, int Ndim)
{
    const int tid = threadIdx.x;
    const int mtile = blockIdx.y, ntile = blockIdx.x;
    const int e = blockIdx.z;

    const int Mcount = g_count[e];
    if (mtile * 128 >= Mcount) return;
    const int* list = g_list + e * TT;
    const __half* hB = (MODE == 2) ? (h_W1 + (size_t)e * FF * CC)
                                   : (h_W2 + (size_t)e * CC * FF);
    const float* biasp = bias + (size_t)e * Ndim;

    __shared__ __align__(16) __half As[128 * 40];
    __shared__ __align__(16) __half Bs[128 * 40];

    const int wid = tid >> 5, lane = tid & 31;
    const int wm = wid & 3, wn = wid >> 2;
    const int g = lane >> 2, t = lane & 3;

    const int arow = tid >> 1;
    const int acol = (tid & 1) * 16;
    const float* aptr = nullptr;
    const __half* aptr_h = nullptr;
    {
        int r = mtile * 128 + arow;
        if (r < Mcount) {
            int slot = list[r];
            if (MODE == 2) aptr   = g_xn2  + (size_t)(slot >> 1) * CC;
            else           aptr_h = g_Hbuf + (size_t)slot * FF;
        }
    }
    const int brow = tid >> 1;
    const int bcol = (tid & 1) * 16;
    const __half* bptr = hB + (size_t)(ntile * 128 + brow) * Kdim + bcol;

    float4 pa0, pa1, pa2, pa3;
    uint4 ha0, ha1, hb0, hb1;
    pa0 = pa1 = pa2 = pa3 = make_float4(0.f, 0.f, 0.f, 0.f);
    ha0 = ha1 = make_uint4(0u, 0u, 0u, 0u);
    if (MODE == 3) {
        if (aptr_h) {
            ha0 = *(const uint4*)(aptr_h + acol);
            ha1 = *(const uint4*)(aptr_h + acol + 8);
        }
    } else if (aptr) {
        pa0 = *(const float4*)(aptr + acol);
        pa1 = *(const float4*)(aptr + acol + 4);
        pa2 = *(const float4*)(aptr + acol + 8);
        pa3 = *(const float4*)(aptr + acol + 12);
    }
    hb0 = *(const uint4*)(bptr);
    hb1 = *(const uint4*)(bptr + 8);

    float acc[2][8][4];
#pragma unroll
    for (int i = 0; i < 2; i++)
#pragma unroll
        for (int j = 0; j < 8; j++)
#pragma unroll
            for (int q = 0; q < 4; q++) acc[i][j][q] = 0.f;

    for (int k0 = 0; k0 < Kdim; k0 += 32) {
        if (MODE == 3) {
            *(uint4*)&As[arow * 40 + acol]     = ha0;
            *(uint4*)&As[arow * 40 + acol + 8] = ha1;
        } else {
            uint4 u0, u1;
            u0.x = packh2(pa0.x, pa0.y); u0.y = packh2(pa0.z, pa0.w);
            u0.z = packh2(pa1.x, pa1.y); u0.w = packh2(pa1.z, pa1.w);
            u1.x = packh2(pa2.x, pa2.y); u1.y = packh2(pa2.z, pa2.w);
            u1.z = packh2(pa3.x, pa3.y); u1.w = packh2(pa3.z, pa3.w);
            *(uint4*)&As[arow * 40 + acol]     = u0;
            *(uint4*)&As[arow * 40 + acol + 8] = u1;
        }
        *(uint4*)&Bs[brow * 40 + bcol]     = hb0;
        *(uint4*)&Bs[brow * 40 + bcol + 8] = hb1;
        __syncthreads();

        if (k0 + 32 < Kdim) {
            if (MODE == 3) {
                if (aptr_h) {
                    ha0 = *(const uint4*)(aptr_h + k0 + 32 + acol);
                    ha1 = *(const uint4*)(aptr_h + k0 + 32 + acol + 8);
                }
            } else if (aptr) {
                pa0 = *(const float4*)(aptr + k0 + 32 + acol);
                pa1 = *(const float4*)(aptr + k0 + 32 + acol + 4);
                pa2 = *(const float4*)(aptr + k0 + 32 + acol + 8);
                pa3 = *(const float4*)(aptr + k0 + 32 + acol + 12);
            }
            hb0 = *(const uint4*)(bptr + k0 + 32);
            hb1 = *(const uint4*)(bptr + k0 + 32 + 8);
        }

#pragma unroll
        for (int ks = 0; ks < 32; ks += 16) {
            unsigned a[2][4];
#pragma unroll
            for (int mi = 0; mi < 2; mi++) {
                int row = wm * 32 + mi * 16 + g;
                const __half* pa  = &As[row * 40 + ks + 2 * t];
                const __half* pa8 = &As[(row + 8) * 40 + ks + 2 * t];
                a[mi][0] = *(const unsigned*)pa;
                a[mi][1] = *(const unsigned*)pa8;
                a[mi][2] = *(const unsigned*)(pa + 8);
                a[mi][3] = *(const unsigned*)(pa8 + 8);
            }
#pragma unroll
            for (int ni = 0; ni < 8; ni++) {
                int n = wn * 64 + ni * 8 + g;
                const __half* pb = &Bs[n * 40 + ks + 2 * t];
                unsigned b0 = *(const unsigned*)pb;
                unsigned b1 = *(const unsigned*)(pb + 8);
                mma_f16(acc[0][ni], a[0], b0, b1);
                mma_f16(acc[1][ni], a[1], b0, b1);
            }
        }
        __syncthreads();
    }

#pragma unroll
    for (int mi = 0; mi < 2; mi++) {
#pragma unroll
        for (int rs = 0; rs < 2; rs++) {
            int m = mtile * 128 + wm * 32 + mi * 16 + g + rs * 8;
            if (m >= Mcount) continue;
            int slot = list[m];
#pragma unroll
            for (int ni = 0; ni < 8; ni++) {
                int n = ntile * 128 + wn * 64 + ni * 8 + 2 * t;
                float v0 = acc[mi][ni][rs * 2], v1 = acc[mi][ni][rs * 2 + 1];
                if (MODE == 2) {
                    __half2 hv = __floats2half2_rn(
                        fmaxf(v0 + biasp[n], 0.f),
                        fmaxf(v1 + biasp[n + 1], 0.f));
                    *(__half2*)(g_Hbuf + (size_t)slot * FF + n) = hv;
                } else {
                    float gte = g_gate[slot];
                    float* op = g_O2 + (size_t)slot * CC + n;
                    *(float2*)op = make_float2(gte * (v0 + biasp[n]),
                                               gte * (v1 + biasp[n + 1]));
                }
            }
        }
    }
}

// ------------------------- Flash attention (causal, tf32 mma) ----------------
__global__ __launch_bounds__(128, 3)
void attn_kernel()
{
    __shared__ float Ks[64 * 68];
    __shared__ float Vs[64 * 68];

    const int qt = gridDim.x - 1 - blockIdx.x;
    const int h  = blockIdx.y;
    const int tid = threadIdx.x;
    const int wid = tid >> 5, lane = tid & 31;
    const int g = lane >> 2, t = lane & 3;
    const int m0 = wid * 16;
    const float scale = 0.03125f;

    const float* Qg = g_q + ((size_t)h * TT + qt * 64) * DD;
#pragma unroll
    for (int j = 0; j < 8; j++) {
        int idx = j * 512 + tid * 4;
        float4 v = *(const float4*)(Qg + idx);
        int r = idx >> 6, d = idx & 63;
        *(float4*)(Ks + r * 68 + d) =
            make_float4(to_tf32(v.x), to_tf32(v.y), to_tf32(v.z), to_tf32(v.w));
    }
    __syncthreads();
    unsigned qfrag[8][4];
#pragma unroll
    for (int ks = 0; ks < 8; ks++) {
        qfrag[ks][0] = __float_as_uint(Ks[(m0 + g) * 68 + ks * 8 + t]);
        qfrag[ks][1] = __float_as_uint(Ks[(m0 + g + 8) * 68 + ks * 8 + t]);
        qfrag[ks][2] = __float_as_uint(Ks[(m0 + g) * 68 + ks * 8 + t + 4]);
        qfrag[ks][3] = __float_as_uint(Ks[(m0 + g + 8) * 68 + ks * 8 + t + 4]);
    }

    float accO[8][4];
#pragma unroll
    for (int i = 0; i < 8; i++)
#pragma unroll
        for (int j = 0; j < 4; j++) accO[i][j] = 0.f;
    float mrow[2] = {-1e30f, -1e30f}, lrow[2] = {0.f, 0.f};

    for (int kt = 0; kt <= qt; kt++) {
        __syncthreads();
        const float* Kg = g_k + ((size_t)h * TT + kt * 64) * DD;
        const float* Vg = g_v + ((size_t)h * TT + kt * 64) * DD;
#pragma unroll
        for (int j = 0; j < 8; j++) {
            int idx = j * 512 + tid * 4;
            int r = idx >> 6, d = idx & 63;
            float4 kv = *(const float4*)(Kg + idx);
            *(float4*)(Ks + r * 68 + d) =
                make_float4(to_tf32(kv.x), to_tf32(kv.y), to_tf32(kv.z), to_tf32(kv.w));
            float4 vv = *(const float4*)(Vg + idx);
            *(float4*)(Vs + r * 68 + d) =
                make_float4(to_tf32(vv.x), to_tf32(vv.y), to_tf32(vv.z), to_tf32(vv.w));
        }
        __syncthreads();

        float sacc[8][4];
#pragma unroll
        for (int i = 0; i < 8; i++)
#pragma unroll
            for (int j = 0; j < 4; j++) sacc[i][j] = 0.f;
#pragma unroll
        for (int ks = 0; ks < 8; ks++) {
#pragma unroll
            for (int ni = 0; ni < 8; ni++) {
                unsigned b[2];
                b[0] = __float_as_uint(Ks[(ni * 8 + g) * 68 + ks * 8 + t]);
                b[1] = __float_as_uint(Ks[(ni * 8 + g) * 68 + ks * 8 + t + 4]);
                mma_tf32(sacc[ni], qfrag[ks], b);
            }
        }

#pragma unroll
        for (int r = 0; r < 2; r++) {
            int rowl = m0 + g + r * 8;
            float vmax = -1e30f;
#pragma unroll
            for (int ni = 0; ni < 8; ni++) {
                float s0 = sacc[ni][r * 2] * scale;
                float s1 = sacc[ni][r * 2 + 1] * scale;
                if (kt == qt) {
                    int c0 = ni * 8 + 2 * t;
                    if (c0 > rowl)     s0 = -1e30f;
                    if (c0 + 1 > rowl) s1 = -1e30f;
                }
                sacc[ni][r * 2] = s0; sacc[ni][r * 2 + 1] = s1;
                vmax = fmaxf(vmax, fmaxf(s0, s1));
            }
            vmax = fmaxf(vmax, __shfl_xor_sync(0xffffffffu, vmax, 1));
            vmax = fmaxf(vmax, __shfl_xor_sync(0xffffffffu, vmax, 2));
            float mn  = fmaxf(mrow[r], vmax);
            float fac = __expf(mrow[r] - mn);
            float sum = 0.f;
#pragma unroll
            for (int ni = 0; ni < 8; ni++) {
                float p0 = __expf(sacc[ni][r * 2] - mn);
                float p1 = __expf(sacc[ni][r * 2 + 1] - mn);
                sacc[ni][r * 2] = p0; sacc[ni][r * 2 + 1] = p1;
                sum += p0 + p1;
            }
            sum += __shfl_xor_sync(0xffffffffu, sum, 1);
            sum += __shfl_xor_sync(0xffffffffu, sum, 2);
            mrow[r] = mn;
            lrow[r] = lrow[r] * fac + sum;
#pragma unroll
            for (int ni = 0; ni < 8; ni++) {
                accO[ni][r * 2]     *= fac;
                accO[ni][r * 2 + 1] *= fac;
            }
        }

        __syncthreads();
        float* Ps = Ks;
#pragma unroll
        for (int ni = 0; ni < 8; ni++) {
            Ps[(m0 + g) * 68 + ni * 8 + 2 * t]         = to_tf32(sacc[ni][0]);
            Ps[(m0 + g) * 68 + ni * 8 + 2 * t + 1]     = to_tf32(sacc[ni][1]);
            Ps[(m0 + g + 8) * 68 + ni * 8 + 2 * t]     = to_tf32(sacc[ni][2]);
            Ps[(m0 + g + 8) * 68 + ni * 8 + 2 * t + 1] = to_tf32(sacc[ni][3]);
        }
        __syncwarp();

#pragma unroll
        for (int ks = 0; ks < 8; ks++) {
            unsigned a[4];
            a[0] = __float_as_uint(Ps[(m0 + g) * 68 + ks * 8 + t]);
            a[1] = __float_as_uint(Ps[(m0 + g + 8) * 68 + ks * 8 + t]);
            a[2] = __float_as_uint(Ps[(m0 + g) * 68 + ks * 8 + t + 4]);
            a[3] = __float_as_uint(Ps[(m0 + g + 8) * 68 + ks * 8 + t + 4]);
#pragma unroll
            for (int ni = 0; ni < 8; ni++) {
                unsigned b[2];
                b[0] = __float_as_uint(Vs[(ks * 8 + t) * 68 + ni * 8 + g]);
                b[1] = __float_as_uint(Vs[(ks * 8 + t + 4) * 68 + ni * 8 + g]);
                mma_tf32(accO[ni], a, b);
            }
        }
    }

#pragma unroll
    for (int r = 0; r < 2; r++) {
        float inv = 1.f / lrow[r];
        int row = qt * 64 + m0 + g + r * 8;
#pragma unroll
        for (int ni = 0; ni < 8; ni++) {
            int col = h * 64 + ni * 8 + 2 * t;
            *(float2*)(g_att + (size_t)row * CC + col) =
                make_float2(accO[ni][r * 2] * inv, accO[ni][r * 2 + 1] * inv);
        }
    }
}

// ------------------------------ Router ---------------------------------------
__global__ void zero_counts_kernel() { if (threadIdx.x < EE) g_count[threadIdx.x] = 0; }

__global__ void router_kernel(const float* __restrict__ Wr, const float* __restrict__ br,
                              const float* __restrict__ Wn, const float* __restrict__ bn,
                              const float* __restrict__ noise)
{
    int t = blockIdx.x * 8 + (threadIdx.x >> 5);
    int lane = threadIdx.x & 31;
    const float* xr = g_xn2 + (size_t)t * CC;
    float ar[8] = {0,0,0,0,0,0,0,0}, an[8] = {0,0,0,0,0,0,0,0};
    for (int c = lane; c < CC; c += 32) {
        float xv = xr[c];
        float4 w0 = *(const float4*)(Wr + c * 8);
        float4 w1 = *(const float4*)(Wr + c * 8 + 4);
        ar[0] += xv * w0.x; ar[1] += xv * w0.y; ar[2] += xv * w0.z; ar[3] += xv * w0.w;
        ar[4] += xv * w1.x; ar[5] += xv * w1.y; ar[6] += xv * w1.z; ar[7] += xv * w1.w;
        float4 n0 = *(const float4*)(Wn + c * 8);
        float4 n1 = *(const float4*)(Wn + c * 8 + 4);
        an[0] += xv * n0.x; an[1] += xv * n0.y; an[2] += xv * n0.z; an[3] += xv * n0.w;
        an[4] += xv * n1.x; an[5] += xv * n1.y; an[6] += xv * n1.z; an[7] += xv * n1.w;
    }
#pragma unroll
    for (int e = 0; e < 8; e++) {
#pragma unroll
        for (int o = 16; o > 0; o >>= 1) {
            ar[e] += __shfl_xor_sync(0xffffffffu, ar[e], o);
            an[e] += __shfl_xor_sync(0xffffffffu, an[e], o);
        }
    }
    if (lane == 0) {
        float noisy[8];
#pragma unroll
        for (int e = 0; e < 8; e++) {
            float l  = ar[e] + br[e];
            float nl = an[e] + bn[e];
            float sp = (nl > 20.f) ? nl : log1pf(expf(nl));
            noisy[e] = l + noise[t * 8 + e] * sp;
        }
        int i1 = 0;
        for (int e = 1; e < 8; e++) if (noisy[e] > noisy[i1]) i1 = e;
        int i2 = (i1 == 0) ? 1 : 0;
        for (int e = 0; e < 8; e++)
            if (e != i1 && noisy[e] > noisy[i2]) i2 = e;
        float ee = expf(noisy[i2] - noisy[i1]);
        float z  = 1.f + ee;
        float g1 = 1.f / z, g2 = ee / z;
        int p1 = atomicAdd(&g_count[i1], 1);
        g_list[i1 * TT + p1] = t * 2;     g_gate[t * 2]     = g1;
        int p2 = atomicAdd(&g_count[i2], 1);
        g_list[i2 * TT + p2] = t * 2 + 1; g_gate[t * 2 + 1] = g2;
    }
}

// ------------------------------ Combine --------------------------------------
__global__ void combine_kernel(float* __restrict__ out)
{
    int t = blockIdx.x;
    size_t b0 = (size_t)(t * 2) * CC;
    size_t b1 = (size_t)(t * 2 + 1) * CC;
    for (int c = threadIdx.x; c < CC; c += 256)
        out[(size_t)t * CC + c] += g_O2[b0 + c] + g_O2[b1 + c];
}

// ------------------------------ launch ---------------------------------------
extern "C" void kernel_launch(void* const* d_in, const int* in_sizes, int n_in,
                              void* d_out, int out_size)
{
    (void)in_sizes; (void)n_in; (void)out_size;
    const float* x     = (const float*)d_in[0];
    const float* noise = (const float*)d_in[1];
    const float* ln1_g = (const float*)d_in[2];
    const float* ln1_b = (const float*)d_in[3];
    const float* ln2_g = (const float*)d_in[4];
    const float* ln2_b = (const float*)d_in[5];
    const float* Wq    = (const float*)d_in[6];
    const float* Wk    = (const float*)d_in[7];
    const float* Wv    = (const float*)d_in[8];
    const float* Wproj = (const float*)d_in[9];
    const float* bproj = (const float*)d_in[10];
    const float* Wr    = (const float*)d_in[11];
    const float* br    = (const float*)d_in[12];
    const float* Wn    = (const float*)d_in[13];
    const float* bn    = (const float*)d_in[14];
    const float* W1    = (const float*)d_in[15];
    const float* b1    = (const float*)d_in[16];
    const float* W2    = (const float*)d_in[17];
    const float* b2    = (const float*)d_in[18];
    float* out = (float*)d_out;

    __half *p_hW1, *p_hW2;
    cudaGetSymbolAddress((void**)&p_hW1, h_W1);
    cudaGetSymbolAddress((void**)&p_hW2, h_W2);

    dim3 tb(32, 8);
    // W1 [e][C][F] -> [e][F][C]
    transpose_h_kernel<<<dim3(FF / 32, CC / 32, EE), tb>>>(
        W1, p_hW1, CC, FF, (size_t)CC * FF, (size_t)FF * CC);
    // W2 [e][F][C] -> [e][C][F]
    transpose_h_kernel<<<dim3(CC / 32, FF / 32, EE), tb>>>(
        W2, p_hW2, FF, CC, (size_t)FF * CC, (size_t)CC * FF);

    ln_kernel<0><<<TT, 256>>>(x, ln1_g, ln1_b);

    // fused QKV (tf32): z = 0/1/2 selects Wq/Wk/Wv
    gemm_kernel<0><<<dim3(CC / 128, TT / 128, 3), 256>>>(
        Wq, Wk, Wv, nullptr, nullptr, nullptr, CC, CC);

    attn_kernel<<<dim3(TT / 64, HH), 128>>>();

    gemm_kernel<1><<<dim3(CC / 128, TT / 128), 256>>>(
        Wproj, nullptr, nullptr, bproj, x, out, CC, CC);

    ln_kernel<1><<<TT, 256>>>(out, ln2_g, ln2_b);

    zero_counts_kernel<<<1, 32>>>();
    router_kernel<<<TT / 8, 256>>>(Wr, br, Wn, bn, noise);

    gemm_h_kernel<2><<<dim3(FF / 128, 16, EE), 256>>>(b1, CC, FF);
    gemm_h_kernel<3><<<dim3(CC / 128, 16, EE), 256>>>(b2, FF, CC);

    combine_kernel<<<TT, 256>>>(out);
}